// round 1
// baseline (speedup 1.0000x reference)
#include <cuda_runtime.h>
#include <math_constants.h>
#include <cstddef>

// Problem constants
#define Bb 2
#define Tt 1024
#define Cc 1024
#define NH 16
#define HS 64
#define BD 16
#define DELTA 64

// Scratch (device globals; no allocation allowed)
__device__ float g_disp[(size_t)Bb * NH * Tt * BD];   // (B,NH,T,BD)
__device__ float g_val [(size_t)Bb * NH * Tt * HS];   // (B,NH,T,HS)
__device__ float g_y   [(size_t)Bb * Tt * Cc];        // (B,T,C)
__device__ float g_pos [DELTA * BD];                  // (64,16)

// ---------------------------------------------------------------------------
// Tiled fp32 GEMM: C[m,n] = bias[n] + sum_k A[m*K+k] * W[n*K+k]
// BM=128, BN=64, BK=16, 256 threads, 8x4 micro-tile.
// MODE 0: scatter to g_disp (B,NH,T,BD); MODE 1: scatter to g_val (B,NH,T,HS);
// MODE 2: A := g_y, plain store to Cout.
// ---------------------------------------------------------------------------
#define GBM 128
#define GBN 64
#define GBK 16
#define GTM 8
#define GTN 4

template<int MODE>
__global__ __launch_bounds__(256) void gemm_kernel(
    const float* __restrict__ A_in,
    const float* __restrict__ W,
    const float* __restrict__ bias,
    float* __restrict__ Cout,
    int M, int N, int K)
{
    __shared__ float As[GBK][GBM + 1];
    __shared__ float Bs[GBK][GBN + 1];

    const float* __restrict__ A = (MODE == 2) ? (const float*)g_y : A_in;

    const int bm = blockIdx.x * GBM;
    const int bn = blockIdx.y * GBN;
    const int tid = threadIdx.x;
    const int tx = tid & 15;   // N dim: 16 * 4 = 64
    const int ty = tid >> 4;   // M dim: 16 * 8 = 128

    float acc[GTM][GTN];
#pragma unroll
    for (int i = 0; i < GTM; i++)
#pragma unroll
        for (int j = 0; j < GTN; j++) acc[i][j] = 0.f;

    for (int k0 = 0; k0 < K; k0 += GBK) {
        // A tile: 128x16 = 512 float4, 2 per thread, stored transposed
#pragma unroll
        for (int t = 0; t < 2; t++) {
            int i = tid + t * 256;
            int row = i >> 2;
            int kq = (i & 3) << 2;
            float4 v = *(const float4*)(A + (size_t)(bm + row) * K + k0 + kq);
            As[kq + 0][row] = v.x; As[kq + 1][row] = v.y;
            As[kq + 2][row] = v.z; As[kq + 3][row] = v.w;
        }
        // B tile: 64x16 = 256 float4, 1 per thread
        {
            int row = tid >> 2;
            int kq = (tid & 3) << 2;
            float4 v = *(const float4*)(W + (size_t)(bn + row) * K + k0 + kq);
            Bs[kq + 0][row] = v.x; Bs[kq + 1][row] = v.y;
            Bs[kq + 2][row] = v.z; Bs[kq + 3][row] = v.w;
        }
        __syncthreads();

#pragma unroll
        for (int kk = 0; kk < GBK; kk++) {
            float ra[GTM], rb[GTN];
#pragma unroll
            for (int i = 0; i < GTM; i++) ra[i] = As[kk][ty * GTM + i];
#pragma unroll
            for (int j = 0; j < GTN; j++) rb[j] = Bs[kk][tx * GTN + j];
#pragma unroll
            for (int i = 0; i < GTM; i++)
#pragma unroll
                for (int j = 0; j < GTN; j++)
                    acc[i][j] += ra[i] * rb[j];
        }
        __syncthreads();
    }

    // Epilogue
#pragma unroll
    for (int i = 0; i < GTM; i++) {
        int m = bm + ty * GTM + i;
        int n0 = bn + tx * GTN;
        float4 v;
        v.x = acc[i][0] + bias[n0 + 0];
        v.y = acc[i][1] + bias[n0 + 1];
        v.z = acc[i][2] + bias[n0 + 2];
        v.w = acc[i][3] + bias[n0 + 3];
        if (MODE == 0) {
            int b = m >> 10, t = m & (Tt - 1);
            int h = n0 >> 4, d = n0 & (BD - 1);   // 4 consecutive d, same h
            *(float4*)(g_disp + ((size_t)((b * NH + h) * Tt + t)) * BD + d) = v;
        } else if (MODE == 1) {
            int b = m >> 10, t = m & (Tt - 1);
            int h = n0 >> 6, e = n0 & (HS - 1);
            *(float4*)(g_val + ((size_t)((b * NH + h) * Tt + t)) * HS + e) = v;
        } else {
            *(float4*)(Cout + (size_t)m * N + n0) = v;
        }
    }
}

// ---------------------------------------------------------------------------
// pos_feat[j,k] = sum_e rel[j,e] * W_pos[k,e]   (64x16)
// ---------------------------------------------------------------------------
__global__ void posfeat_kernel(const float* __restrict__ rel,
                               const float* __restrict__ Wpos)
{
    int i = threadIdx.x;          // 0..1023
    int j = i >> 4, k = i & 15;
    float s = 0.f;
#pragma unroll
    for (int e = 0; e < BD; e++) s += rel[j * BD + e] * Wpos[k * BD + e];
    g_pos[j * BD + k] = s;
}

// ---------------------------------------------------------------------------
// Attention: one block (64 threads) per (b,h,t).
// ---------------------------------------------------------------------------
__device__ __forceinline__ float gelu_exact(float z) {
    return 0.5f * z * (1.f + erff(z * 0.70710678118654752440f));
}

__global__ __launch_bounds__(64) void attn_kernel(
    const float* __restrict__ W_fused, const float* __restrict__ b_fused,
    const float* __restrict__ W_bond,  const float* __restrict__ b_bond,
    const float* __restrict__ W_dmg,   const float* __restrict__ b_dmg)
{
    const int bid = blockIdx.x;
    const int t = bid & (Tt - 1);
    const int h = (bid >> 10) & (NH - 1);
    const int b = bid >> 14;
    const int tid = threadIdx.x;

    __shared__ float wdT[BD][DELTA + 1];   // transposed disp window [d][j]
    __shared__ float pfT[BD][DELTA + 1];   // transposed pos_feat   [k][j]
    __shared__ float Wfs[2 * BD * BD];     // 512 floats, [32][16]
    __shared__ float redw[DELTA];

    const float* __restrict__ dispbase = g_disp + ((size_t)(b * NH + h) * Tt) * BD;

    // cooperative window load: 64 rows x 16 floats = 256 float4
#pragma unroll
    for (int it = 0; it < 4; it++) {
        int idx = tid + it * 64;
        int row = idx >> 2;
        int dq = (idx & 3) << 2;
        int tp = t - (DELTA - 1) + row;
        float4 v = make_float4(0.f, 0.f, 0.f, 0.f);
        if (tp >= 0) v = *(const float4*)(dispbase + (size_t)tp * BD + dq);
        wdT[dq + 0][row] = v.x; wdT[dq + 1][row] = v.y;
        wdT[dq + 2][row] = v.z; wdT[dq + 3][row] = v.w;
    }
    // pos_feat load (transposed)
#pragma unroll
    for (int it = 0; it < 4; it++) {
        int idx = tid + it * 64;
        int row = idx >> 2;
        int dq = (idx & 3) << 2;
        float4 v = *(const float4*)(g_pos + row * BD + dq);
        pfT[dq + 0][row] = v.x; pfT[dq + 1][row] = v.y;
        pfT[dq + 2][row] = v.z; pfT[dq + 3][row] = v.w;
    }
    // W_fused: 128 float4
#pragma unroll
    for (int it = 0; it < 2; it++) {
        int idx = tid + it * 64;
        *(float4*)(Wfs + idx * 4) = *(const float4*)(W_fused + idx * 4);
    }
    __syncthreads();

    const int j = tid;
    const int tp = t - (DELTA - 1) + j;

    float strain[BD], pf[BD];
#pragma unroll
    for (int d = 0; d < BD; d++) {
        strain[d] = wdT[d][j] - wdT[d][DELTA - 1];
        pf[d] = pfT[d][j];
    }

    float bond = 0.f, dmg = 0.f;
#pragma unroll
    for (int k = 0; k < BD; k++) {
        float zb = b_fused[k];
        float zd = b_fused[BD + k];
#pragma unroll
        for (int d = 0; d < BD; d++) {
            zb += strain[d] * Wfs[k * BD + d];
            zd += strain[d] * Wfs[(BD + k) * BD + d];
        }
        zb += pf[k];
        bond += gelu_exact(zb) * W_bond[k];
        dmg  += gelu_exact(zd) * W_dmg[k];
    }

    float sig = 1.f / (1.f + expf(-(dmg + b_dmg[0])));
    float logit = bond + b_bond[0] - 10.f * sig;
    if (tp < 0) logit = -CUDART_INF_F;

    // softmax over 64 window positions
    redw[j] = logit;
    __syncthreads();
    float mx = -CUDART_INF_F;
#pragma unroll
    for (int jj = 0; jj < DELTA; jj++) mx = fmaxf(mx, redw[jj]);
    __syncthreads();
    float w = (tp >= 0) ? expf(logit - mx) : 0.f;
    redw[j] = w;
    __syncthreads();
    float s = 0.f;
#pragma unroll
    for (int jj = 0; jj < DELTA; jj++) s += redw[jj];
    float inv = 1.f / s;

    // weighted sum of val window; thread index is now the HS channel e
    const float* __restrict__ valbase = g_val + ((size_t)(b * NH + h) * Tt) * HS;
    const int e = tid;
    float acc = 0.f;
    const int j0 = (t >= DELTA - 1) ? 0 : (DELTA - 1 - t);
#pragma unroll 8
    for (int jj = j0; jj < DELTA; jj++)
        acc += redw[jj] * valbase[(size_t)(t - (DELTA - 1) + jj) * HS + e];

    g_y[((size_t)(b * Tt + t)) * Cc + h * HS + e] = acc * inv;
}

// ---------------------------------------------------------------------------
// Launch
// ---------------------------------------------------------------------------
extern "C" void kernel_launch(void* const* d_in, const int* in_sizes, int n_in,
                              void* d_out, int out_size)
{
    const float* x       = (const float*)d_in[0];
    const float* W_disp  = (const float*)d_in[1];
    const float* b_disp  = (const float*)d_in[2];
    const float* W_val   = (const float*)d_in[3];
    const float* b_val   = (const float*)d_in[4];
    const float* rel     = (const float*)d_in[5];
    const float* W_fused = (const float*)d_in[6];
    const float* b_fused = (const float*)d_in[7];
    const float* W_pos   = (const float*)d_in[8];
    const float* W_bond  = (const float*)d_in[9];
    const float* b_bond  = (const float*)d_in[10];
    const float* W_dmg   = (const float*)d_in[11];
    const float* b_dmg   = (const float*)d_in[12];
    const float* W_cproj = (const float*)d_in[13];
    const float* b_cproj = (const float*)d_in[14];
    float* out = (float*)d_out;

    const int M = Bb * Tt;   // 2048
    const int K = Cc;        // 1024

    dim3 gd(M / GBM, (NH * BD) / GBN);   // 16 x 4
    gemm_kernel<0><<<gd, 256>>>(x, W_disp, b_disp, nullptr, M, NH * BD, K);

    dim3 gv(M / GBM, Cc / GBN);          // 16 x 16
    gemm_kernel<1><<<gv, 256>>>(x, W_val, b_val, nullptr, M, Cc, K);

    posfeat_kernel<<<1, DELTA * BD>>>(rel, W_pos);

    attn_kernel<<<Bb * NH * Tt, DELTA>>>(W_fused, b_fused, W_bond, b_bond,
                                         W_dmg, b_dmg);

    dim3 gc(M / GBM, Cc / GBN);          // 16 x 16
    gemm_kernel<2><<<gc, 256>>>(nullptr, W_cproj, b_cproj, out, M, Cc, K);
}

// round 2
// speedup vs baseline: 1.2629x; 1.2629x over previous
#include <cuda_runtime.h>
#include <math_constants.h>
#include <cstddef>

// Problem constants
#define Bb 2
#define Tt 1024
#define Cc 1024
#define NH 16
#define HS 64
#define BD 16
#define DELTA 64

// Scratch (device globals; no allocation allowed)
__device__ float g_disp[(size_t)Bb * NH * Tt * BD];   // (B,NH,T,BD)
__device__ float g_val [(size_t)Bb * NH * Tt * HS];   // (B,NH,T,HS)
__device__ float g_Q   [(size_t)Bb * NH * Tt * 32];   // (B,NH,T,32) = disp @ W_fused^T
__device__ float g_y   [(size_t)Bb * Tt * Cc];        // (B,T,C)
__device__ float g_pos [DELTA * BD];                  // (64,16)

// ---------------------------------------------------------------------------
// Tiled fp32 GEMM: C[m,n] = bias[n] + sum_k A[m*K+k] * W[n*K+k]
// BM=128, BN=64, BK=16, 256 threads, 8x4 micro-tile.
// MODE 0: scatter to g_disp (B,NH,T,BD); MODE 1: scatter to g_val (B,NH,T,HS);
// MODE 2: A := g_y, plain store to Cout.
// ---------------------------------------------------------------------------
#define GBM 128
#define GBN 64
#define GBK 16
#define GTM 8
#define GTN 4

template<int MODE>
__global__ __launch_bounds__(256) void gemm_kernel(
    const float* __restrict__ A_in,
    const float* __restrict__ W,
    const float* __restrict__ bias,
    float* __restrict__ Cout,
    int M, int N, int K)
{
    __shared__ float As[GBK][GBM + 1];
    __shared__ float Bs[GBK][GBN + 1];

    const float* __restrict__ A = (MODE == 2) ? (const float*)g_y : A_in;

    const int bm = blockIdx.x * GBM;
    const int bn = blockIdx.y * GBN;
    const int tid = threadIdx.x;
    const int tx = tid & 15;   // N dim: 16 * 4 = 64
    const int ty = tid >> 4;   // M dim: 16 * 8 = 128

    float acc[GTM][GTN];
#pragma unroll
    for (int i = 0; i < GTM; i++)
#pragma unroll
        for (int j = 0; j < GTN; j++) acc[i][j] = 0.f;

    for (int k0 = 0; k0 < K; k0 += GBK) {
#pragma unroll
        for (int t = 0; t < 2; t++) {
            int i = tid + t * 256;
            int row = i >> 2;
            int kq = (i & 3) << 2;
            float4 v = *(const float4*)(A + (size_t)(bm + row) * K + k0 + kq);
            As[kq + 0][row] = v.x; As[kq + 1][row] = v.y;
            As[kq + 2][row] = v.z; As[kq + 3][row] = v.w;
        }
        {
            int row = tid >> 2;
            int kq = (tid & 3) << 2;
            float4 v = *(const float4*)(W + (size_t)(bn + row) * K + k0 + kq);
            Bs[kq + 0][row] = v.x; Bs[kq + 1][row] = v.y;
            Bs[kq + 2][row] = v.z; Bs[kq + 3][row] = v.w;
        }
        __syncthreads();

#pragma unroll
        for (int kk = 0; kk < GBK; kk++) {
            float ra[GTM], rb[GTN];
#pragma unroll
            for (int i = 0; i < GTM; i++) ra[i] = As[kk][ty * GTM + i];
#pragma unroll
            for (int j = 0; j < GTN; j++) rb[j] = Bs[kk][tx * GTN + j];
#pragma unroll
            for (int i = 0; i < GTM; i++)
#pragma unroll
                for (int j = 0; j < GTN; j++)
                    acc[i][j] += ra[i] * rb[j];
        }
        __syncthreads();
    }

#pragma unroll
    for (int i = 0; i < GTM; i++) {
        int m = bm + ty * GTM + i;
        int n0 = bn + tx * GTN;
        float4 v;
        v.x = acc[i][0] + bias[n0 + 0];
        v.y = acc[i][1] + bias[n0 + 1];
        v.z = acc[i][2] + bias[n0 + 2];
        v.w = acc[i][3] + bias[n0 + 3];
        if (MODE == 0) {
            int b = m >> 10, t = m & (Tt - 1);
            int h = n0 >> 4, d = n0 & (BD - 1);
            *(float4*)(g_disp + ((size_t)((b * NH + h) * Tt + t)) * BD + d) = v;
        } else if (MODE == 1) {
            int b = m >> 10, t = m & (Tt - 1);
            int h = n0 >> 6, e = n0 & (HS - 1);
            *(float4*)(g_val + ((size_t)((b * NH + h) * Tt + t)) * HS + e) = v;
        } else {
            *(float4*)(Cout + (size_t)m * N + n0) = v;
        }
    }
}

// ---------------------------------------------------------------------------
// pos_feat[j,k] = sum_e rel[j,e] * W_pos[k,e]   (64x16)
// ---------------------------------------------------------------------------
__global__ void posfeat_kernel(const float* __restrict__ rel,
                               const float* __restrict__ Wpos)
{
    int i = threadIdx.x;
    int j = i >> 4, k = i & 15;
    float s = 0.f;
#pragma unroll
    for (int e = 0; e < BD; e++) s += rel[j * BD + e] * Wpos[k * BD + e];
    g_pos[j * BD + k] = s;
}

// ---------------------------------------------------------------------------
// qproj: g_Q[token][o] = sum_d W_fused[o][d] * g_disp[token][d]  (o = 0..31)
// ---------------------------------------------------------------------------
__global__ __launch_bounds__(256) void qproj_kernel(const float* __restrict__ Wf)
{
    __shared__ float Wfs[32 * BD];
    int tid = threadIdx.x;
    for (int i = tid; i < 32 * BD; i += 256) Wfs[i] = Wf[i];
    __syncthreads();

    size_t token = (size_t)blockIdx.x * 256 + tid;
    float d[BD];
    const float4* dp = (const float4*)(g_disp + token * BD);
#pragma unroll
    for (int q = 0; q < 4; q++) {
        float4 v = dp[q];
        d[q * 4 + 0] = v.x; d[q * 4 + 1] = v.y;
        d[q * 4 + 2] = v.z; d[q * 4 + 3] = v.w;
    }
    float* qout = g_Q + token * 32;
#pragma unroll
    for (int o4 = 0; o4 < 8; o4++) {
        float4 r;
        float s0 = 0.f, s1 = 0.f, s2 = 0.f, s3 = 0.f;
#pragma unroll
        for (int dd = 0; dd < BD; dd++) {
            s0 += Wfs[(o4 * 4 + 0) * BD + dd] * d[dd];
            s1 += Wfs[(o4 * 4 + 1) * BD + dd] * d[dd];
            s2 += Wfs[(o4 * 4 + 2) * BD + dd] * d[dd];
            s3 += Wfs[(o4 * 4 + 3) * BD + dd] * d[dd];
        }
        r.x = s0; r.y = s1; r.z = s2; r.w = s3;
        *(float4*)(qout + o4 * 4) = r;
    }
}

// ---------------------------------------------------------------------------
// Attention: one block (256 threads) per (b,h, 64-wide t-tile).
// ---------------------------------------------------------------------------
struct AttnSmem {
    float QsT[32][132];    // QsT[k][r] = Q[t0-63+r][k], r = 0..126
    float posB[16][64];    // posB[k][j] = pos_feat[j][k] + b_fused[k]
    float Wbs[16];
    float Wds[16];
    float Vs[127][64];     // Vs[r][e] = val[t0-63+r][e]
    float Wt[64][68];      // logits -> weights, padded row
};

__device__ __forceinline__ float gelu_t(float z) {
    float arg = z * (0.7978845608f + 0.0356774081f * z * z);
    float th;
    asm("tanh.approx.f32 %0, %1;" : "=f"(th) : "f"(arg));
    return 0.5f * z * (1.f + th);
}

__global__ __launch_bounds__(256) void attn_kernel(
    const float* __restrict__ b_fused,
    const float* __restrict__ W_bond, const float* __restrict__ b_bond,
    const float* __restrict__ W_dmg,  const float* __restrict__ b_dmg)
{
    extern __shared__ char smraw[];
    AttnSmem& sm = *reinterpret_cast<AttnSmem*>(smraw);

    const int bid = blockIdx.x;          // ((b*NH + h) * 16 + tile)
    const int tile = bid & 15;
    const int bh = bid >> 4;
    const int t0 = tile * 64;
    const int tid = threadIdx.x;

    const float* __restrict__ Qbase = g_Q + (size_t)bh * Tt * 32;
    const float* __restrict__ Vbase = g_val + (size_t)bh * Tt * HS;

    // Q window load (transposed into smem)
    for (int i = tid; i < 127 * 8; i += 256) {
        int r = i >> 3, kq = (i & 7) << 2;
        int tp = t0 - 63 + r;
        float4 v = make_float4(0.f, 0.f, 0.f, 0.f);
        if (tp >= 0) v = *(const float4*)(Qbase + (size_t)tp * 32 + kq);
        sm.QsT[kq + 0][r] = v.x; sm.QsT[kq + 1][r] = v.y;
        sm.QsT[kq + 2][r] = v.z; sm.QsT[kq + 3][r] = v.w;
    }
    // posB (fold b_fused bond bias)
    for (int i = tid; i < 16 * 64; i += 256) {
        int k = i >> 6, j = i & 63;
        sm.posB[k][j] = g_pos[j * BD + k] + b_fused[k];
    }
    if (tid < 16) { sm.Wbs[tid] = W_bond[tid]; sm.Wds[tid] = W_dmg[tid]; }
    // V window
    for (int i = tid; i < 127 * 16; i += 256) {
        int r = i >> 4, eq = (i & 15) << 2;
        int tp = t0 - 63 + r;
        float4 v = make_float4(0.f, 0.f, 0.f, 0.f);
        if (tp >= 0) v = *(const float4*)(Vbase + (size_t)tp * HS + eq);
        *(float4*)&sm.Vs[r][eq] = v;
    }
    __syncthreads();

    // ---- logits: thread (tq, jc) handles t_local=tq, j in [jc*16, jc*16+16) ----
    const int tq = tid & 63;
    const int jc = tid >> 6;
    const int c = tq + 63;               // center row

    float bond[16], dmg[16];
#pragma unroll
    for (int jj = 0; jj < 16; jj++) { bond[jj] = 0.f; dmg[jj] = 0.f; }

#pragma unroll
    for (int k = 0; k < 16; k++) {
        float qbc = sm.QsT[k][c];
        float qdc = sm.QsT[16 + k][c] - b_fused[16 + k];
        float wb = sm.Wbs[k];
        float wd = sm.Wds[k];
#pragma unroll
        for (int jj = 0; jj < 16; jj++) {
            int j = jc * 16 + jj;
            int r = tq + j;
            float db = sm.QsT[k][r] - qbc + sm.posB[k][j];
            float dd = sm.QsT[16 + k][r] - qdc;
            bond[jj] += gelu_t(db) * wb;
            dmg[jj]  += gelu_t(dd) * wd;
        }
    }
    {
        float bb = b_bond[0];
        float bdm = b_dmg[0];
#pragma unroll
        for (int jj = 0; jj < 16; jj++) {
            int j = jc * 16 + jj;
            float sig = 1.f / (1.f + __expf(-(dmg[jj] + bdm)));
            float logit = bond[jj] + bb - 10.f * sig;
            if (t0 + tq - 63 + j < 0) logit = -CUDART_INF_F;
            sm.Wt[tq][j] = logit;
        }
    }
    __syncthreads();

    // ---- softmax per t (threads 0..63) ----
    if (tid < 64) {
        float mx = -CUDART_INF_F;
#pragma unroll
        for (int j = 0; j < 64; j++) mx = fmaxf(mx, sm.Wt[tid][j]);
        float s = 0.f;
#pragma unroll
        for (int j = 0; j < 64; j++) {
            float e = __expf(sm.Wt[tid][j] - mx);
            sm.Wt[tid][j] = e;
            s += e;
        }
        float inv = 1.f / s;
#pragma unroll
        for (int j = 0; j < 64; j++) sm.Wt[tid][j] *= inv;
    }
    __syncthreads();

    // ---- AV: warp w handles t in {8w..8w+7}, lane covers e-pair ----
    const int wrp = tid >> 5;
    const int l = tid & 31;
    const int b = bh >> 4;       // bh = b*NH + h
    const int h = bh & (NH - 1);

    for (int q = 0; q < 8; q++) {
        int t = wrp * 8 + q;
        float ax = 0.f, ay = 0.f;
#pragma unroll
        for (int j = 0; j < 64; j += 4) {
            float4 wv = *(const float4*)&sm.Wt[t][j];
            {
                float2 v = *(const float2*)&sm.Vs[t + j + 0][2 * l];
                ax += wv.x * v.x; ay += wv.x * v.y;
            }
            {
                float2 v = *(const float2*)&sm.Vs[t + j + 1][2 * l];
                ax += wv.y * v.x; ay += wv.y * v.y;
            }
            {
                float2 v = *(const float2*)&sm.Vs[t + j + 2][2 * l];
                ax += wv.z * v.x; ay += wv.z * v.y;
            }
            {
                float2 v = *(const float2*)&sm.Vs[t + j + 3][2 * l];
                ax += wv.w * v.x; ay += wv.w * v.y;
            }
        }
        float2 o; o.x = ax; o.y = ay;
        *(float2*)(g_y + ((size_t)(b * Tt + t0 + t)) * Cc + h * HS + 2 * l) = o;
    }
}

// ---------------------------------------------------------------------------
// Launch
// ---------------------------------------------------------------------------
extern "C" void kernel_launch(void* const* d_in, const int* in_sizes, int n_in,
                              void* d_out, int out_size)
{
    const float* x       = (const float*)d_in[0];
    const float* W_disp  = (const float*)d_in[1];
    const float* b_disp  = (const float*)d_in[2];
    const float* W_val   = (const float*)d_in[3];
    const float* b_val   = (const float*)d_in[4];
    const float* rel     = (const float*)d_in[5];
    const float* W_fused = (const float*)d_in[6];
    const float* b_fused = (const float*)d_in[7];
    const float* W_pos   = (const float*)d_in[8];
    const float* W_bond  = (const float*)d_in[9];
    const float* b_bond  = (const float*)d_in[10];
    const float* W_dmg   = (const float*)d_in[11];
    const float* b_dmg   = (const float*)d_in[12];
    const float* W_cproj = (const float*)d_in[13];
    const float* b_cproj = (const float*)d_in[14];
    float* out = (float*)d_out;

    const int M = Bb * Tt;   // 2048
    const int K = Cc;        // 1024

    dim3 gd(M / GBM, (NH * BD) / GBN);   // 16 x 4
    gemm_kernel<0><<<gd, 256>>>(x, W_disp, b_disp, nullptr, M, NH * BD, K);

    dim3 gv(M / GBM, Cc / GBN);          // 16 x 16
    gemm_kernel<1><<<gv, 256>>>(x, W_val, b_val, nullptr, M, Cc, K);

    posfeat_kernel<<<1, DELTA * BD>>>(rel, W_pos);

    qproj_kernel<<<(Bb * NH * Tt) / 256, 256>>>(W_fused);

    cudaFuncSetAttribute(attn_kernel, cudaFuncAttributeMaxDynamicSharedMemorySize,
                         (int)sizeof(AttnSmem));
    attn_kernel<<<Bb * NH * (Tt / DELTA), 256, sizeof(AttnSmem)>>>(
        b_fused, W_bond, b_bond, W_dmg, b_dmg);

    dim3 gc(M / GBM, Cc / GBN);          // 16 x 16
    gemm_kernel<2><<<gc, 256>>>(nullptr, W_cproj, b_cproj, out, M, Cc, K);
}

// round 4
// speedup vs baseline: 1.3870x; 1.0983x over previous
#include <cuda_runtime.h>
#include <math_constants.h>
#include <cstddef>

// Problem constants
#define Bb 2
#define Tt 1024
#define Cc 1024
#define NH 16
#define HS 64
#define BD 16
#define DELTA 64

// Scratch (device globals; no allocation allowed)
__device__ float g_disp[(size_t)Bb * NH * Tt * BD];   // (B,NH,T,BD)
__device__ float g_val [(size_t)Bb * NH * Tt * HS];   // (B,NH,T,HS)
__device__ float g_Q   [(size_t)Bb * NH * Tt * 32];   // (B,NH,T,32) = disp @ W_fused^T
__device__ float g_y   [(size_t)Bb * Tt * Cc];        // (B,T,C)
__device__ float g_pos [DELTA * BD];                  // (64,16)

// ---------------------------------------------------------------------------
// Packed f32x2 helpers (Blackwell sm_103a)
// ---------------------------------------------------------------------------
__device__ __forceinline__ unsigned long long pack2(float lo, float hi) {
    unsigned long long r;
    asm("mov.b64 %0, {%1, %2};" : "=l"(r) : "f"(lo), "f"(hi));
    return r;
}
__device__ __forceinline__ void unpack2(unsigned long long v, float& lo, float& hi) {
    asm("mov.b64 {%0, %1}, %2;" : "=f"(lo), "=f"(hi) : "l"(v));
}
__device__ __forceinline__ void fma2(unsigned long long& acc,
                                     unsigned long long a, unsigned long long b) {
    asm("fma.rn.f32x2 %0, %1, %2, %0;" : "+l"(acc) : "l"(a), "l"(b));
}

// ---------------------------------------------------------------------------
// Tiled fp32 GEMM with packed f32x2 FMA:
//   C[m,n] = bias[n] + sum_k A[m*K+k] * W[n*K+k]
// BM=128, BN=64, BK=16, 256 threads.
// Micro-tile per thread: 8 M (as 4 f32x2 pairs) x 4 N (strided by 16).
// MODE 0: scatter to g_disp; MODE 1: scatter to g_val; MODE 2: A := g_y -> Cout.
// ---------------------------------------------------------------------------
#define GBM 128
#define GBN 64
#define GBK 16

template<int MODE>
__global__ __launch_bounds__(256) void gemm_kernel(
    const float* __restrict__ A_in,
    const float* __restrict__ W,
    const float* __restrict__ bias,
    float* __restrict__ Cout,
    int M, int N, int K)
{
    __shared__ float As[GBK][GBM + 2];   // +2 keeps float2 alignment (even stride)
    __shared__ float Bs[GBK][GBN + 1];

    const float* __restrict__ A = (MODE == 2) ? (const float*)g_y : A_in;

    const int bm = blockIdx.x * GBM;
    const int bn = blockIdx.y * GBN;
    const int tid = threadIdx.x;
    const int tx = tid & 15;   // n base; covers n = tx + 16j, j=0..3
    const int ty = tid >> 4;   // m base = ty*8

    unsigned long long acc[4][4];
#pragma unroll
    for (int p = 0; p < 4; p++)
#pragma unroll
        for (int j = 0; j < 4; j++) acc[p][j] = 0ULL;

    for (int k0 = 0; k0 < K; k0 += GBK) {
        // A tile: 128x16 = 512 float4, 2 per thread, transposed into smem
#pragma unroll
        for (int t = 0; t < 2; t++) {
            int i = tid + t * 256;
            int row = i >> 2;
            int kq = (i & 3) << 2;
            float4 v = *(const float4*)(A + (size_t)(bm + row) * K + k0 + kq);
            As[kq + 0][row] = v.x; As[kq + 1][row] = v.y;
            As[kq + 2][row] = v.z; As[kq + 3][row] = v.w;
        }
        // B tile: 64x16 = 256 float4, 1 per thread, transposed
        {
            int row = tid >> 2;
            int kq = (tid & 3) << 2;
            float4 v = *(const float4*)(W + (size_t)(bn + row) * K + k0 + kq);
            Bs[kq + 0][row] = v.x; Bs[kq + 1][row] = v.y;
            Bs[kq + 2][row] = v.z; Bs[kq + 3][row] = v.w;
        }
        __syncthreads();

#pragma unroll
        for (int kk = 0; kk < GBK; kk++) {
            unsigned long long a2[4];
#pragma unroll
            for (int p = 0; p < 4; p++)
                a2[p] = *(const unsigned long long*)&As[kk][ty * 8 + 2 * p];
            unsigned long long b2[4];
#pragma unroll
            for (int j = 0; j < 4; j++) {
                float bv = Bs[kk][tx + 16 * j];
                b2[j] = pack2(bv, bv);
            }
#pragma unroll
            for (int p = 0; p < 4; p++)
#pragma unroll
                for (int j = 0; j < 4; j++)
                    fma2(acc[p][j], a2[p], b2[j]);
        }
        __syncthreads();
    }

    // Epilogue: outputs (m0, m0+1) x n, n = bn + tx + 16j
#pragma unroll
    for (int j = 0; j < 4; j++) {
        int n = bn + tx + 16 * j;
        float bval = bias[n];
#pragma unroll
        for (int p = 0; p < 4; p++) {
            float lo, hi;
            unpack2(acc[p][j], lo, hi);
            lo += bval; hi += bval;
            int m0 = bm + ty * 8 + 2 * p;
            if (MODE == 0) {
                int h = n >> 4, d = n & (BD - 1);
                {
                    int b = m0 >> 10, t = m0 & (Tt - 1);
                    g_disp[((size_t)((b * NH + h) * Tt + t)) * BD + d] = lo;
                }
                {
                    int m1 = m0 + 1;
                    int b = m1 >> 10, t = m1 & (Tt - 1);
                    g_disp[((size_t)((b * NH + h) * Tt + t)) * BD + d] = hi;
                }
            } else if (MODE == 1) {
                int h = n >> 6, e = n & (HS - 1);
                {
                    int b = m0 >> 10, t = m0 & (Tt - 1);
                    g_val[((size_t)((b * NH + h) * Tt + t)) * HS + e] = lo;
                }
                {
                    int m1 = m0 + 1;
                    int b = m1 >> 10, t = m1 & (Tt - 1);
                    g_val[((size_t)((b * NH + h) * Tt + t)) * HS + e] = hi;
                }
            } else {
                Cout[(size_t)m0 * N + n] = lo;
                Cout[(size_t)(m0 + 1) * N + n] = hi;
            }
        }
    }
}

// ---------------------------------------------------------------------------
// pos_feat[j,k] = sum_e rel[j,e] * W_pos[k,e]   (64x16)
// ---------------------------------------------------------------------------
__global__ void posfeat_kernel(const float* __restrict__ rel,
                               const float* __restrict__ Wpos)
{
    int i = threadIdx.x;
    int j = i >> 4, k = i & 15;
    float s = 0.f;
#pragma unroll
    for (int e = 0; e < BD; e++) s += rel[j * BD + e] * Wpos[k * BD + e];
    g_pos[j * BD + k] = s;
}

// ---------------------------------------------------------------------------
// qproj: g_Q[token][o] = sum_d W_fused[o][d] * g_disp[token][d]  (o = 0..31)
// ---------------------------------------------------------------------------
__global__ __launch_bounds__(256) void qproj_kernel(const float* __restrict__ Wf)
{
    __shared__ float Wfs[32 * BD];
    int tid = threadIdx.x;
    for (int i = tid; i < 32 * BD; i += 256) Wfs[i] = Wf[i];
    __syncthreads();

    size_t token = (size_t)blockIdx.x * 256 + tid;
    float d[BD];
    const float4* dp = (const float4*)(g_disp + token * BD);
#pragma unroll
    for (int q = 0; q < 4; q++) {
        float4 v = dp[q];
        d[q * 4 + 0] = v.x; d[q * 4 + 1] = v.y;
        d[q * 4 + 2] = v.z; d[q * 4 + 3] = v.w;
    }
    float* qout = g_Q + token * 32;
#pragma unroll
    for (int o4 = 0; o4 < 8; o4++) {
        float4 r;
        float s0 = 0.f, s1 = 0.f, s2 = 0.f, s3 = 0.f;
#pragma unroll
        for (int dd = 0; dd < BD; dd++) {
            s0 += Wfs[(o4 * 4 + 0) * BD + dd] * d[dd];
            s1 += Wfs[(o4 * 4 + 1) * BD + dd] * d[dd];
            s2 += Wfs[(o4 * 4 + 2) * BD + dd] * d[dd];
            s3 += Wfs[(o4 * 4 + 3) * BD + dd] * d[dd];
        }
        r.x = s0; r.y = s1; r.z = s2; r.w = s3;
        *(float4*)(qout + o4 * 4) = r;
    }
}

// ---------------------------------------------------------------------------
// Attention: one block (256 threads) per (b,h, 64-wide t-tile).
// ---------------------------------------------------------------------------
struct AttnSmem {
    float QsT[32][132];    // QsT[k][r] = Q[t0-63+r][k], r = 0..126
    float posB[16][64];    // posB[k][j] = pos_feat[j][k] + b_fused[k]
    float Wbs[16];
    float Wds[16];
    float Vs[127][64];     // Vs[r][e] = val[t0-63+r][e]
    float Wt[64][68];      // logits -> weights, padded row
};

__device__ __forceinline__ float gelu_t(float z) {
    float arg = z * (0.7978845608f + 0.0356774081f * z * z);
    float th;
    asm("tanh.approx.f32 %0, %1;" : "=f"(th) : "f"(arg));
    return 0.5f * z * (1.f + th);
}

__global__ __launch_bounds__(256) void attn_kernel(
    const float* __restrict__ b_fused,
    const float* __restrict__ W_bond, const float* __restrict__ b_bond,
    const float* __restrict__ W_dmg,  const float* __restrict__ b_dmg)
{
    extern __shared__ char smraw[];
    AttnSmem& sm = *reinterpret_cast<AttnSmem*>(smraw);

    const int bid = blockIdx.x;          // ((b*NH + h) * 16 + tile)
    const int tile = bid & 15;
    const int bh = bid >> 4;
    const int t0 = tile * 64;
    const int tid = threadIdx.x;

    const float* __restrict__ Qbase = g_Q + (size_t)bh * Tt * 32;
    const float* __restrict__ Vbase = g_val + (size_t)bh * Tt * HS;

    // Q window load (transposed into smem)
    for (int i = tid; i < 127 * 8; i += 256) {
        int r = i >> 3, kq = (i & 7) << 2;
        int tp = t0 - 63 + r;
        float4 v = make_float4(0.f, 0.f, 0.f, 0.f);
        if (tp >= 0) v = *(const float4*)(Qbase + (size_t)tp * 32 + kq);
        sm.QsT[kq + 0][r] = v.x; sm.QsT[kq + 1][r] = v.y;
        sm.QsT[kq + 2][r] = v.z; sm.QsT[kq + 3][r] = v.w;
    }
    // posB (fold b_fused bond bias)
    for (int i = tid; i < 16 * 64; i += 256) {
        int k = i >> 6, j = i & 63;
        sm.posB[k][j] = g_pos[j * BD + k] + b_fused[k];
    }
    if (tid < 16) { sm.Wbs[tid] = W_bond[tid]; sm.Wds[tid] = W_dmg[tid]; }
    // V window
    for (int i = tid; i < 127 * 16; i += 256) {
        int r = i >> 4, eq = (i & 15) << 2;
        int tp = t0 - 63 + r;
        float4 v = make_float4(0.f, 0.f, 0.f, 0.f);
        if (tp >= 0) v = *(const float4*)(Vbase + (size_t)tp * HS + eq);
        *(float4*)&sm.Vs[r][eq] = v;
    }
    __syncthreads();

    // ---- logits: thread (tq, jc) handles t_local=tq, j in [jc*16, jc*16+16) ----
    const int tq = tid & 63;
    const int jc = tid >> 6;
    const int c = tq + 63;               // center row

    float bond[16], dmg[16];
#pragma unroll
    for (int jj = 0; jj < 16; jj++) { bond[jj] = 0.f; dmg[jj] = 0.f; }

#pragma unroll
    for (int k = 0; k < 16; k++) {
        float qbc = sm.QsT[k][c];
        float qdc = sm.QsT[16 + k][c] - b_fused[16 + k];
        float wb = sm.Wbs[k];
        float wd = sm.Wds[k];
#pragma unroll
        for (int jj = 0; jj < 16; jj++) {
            int j = jc * 16 + jj;
            int r = tq + j;
            float db = sm.QsT[k][r] - qbc + sm.posB[k][j];
            float dd = sm.QsT[16 + k][r] - qdc;
            bond[jj] += gelu_t(db) * wb;
            dmg[jj]  += gelu_t(dd) * wd;
        }
    }
    {
        float bb = b_bond[0];
        float bdm = b_dmg[0];
#pragma unroll
        for (int jj = 0; jj < 16; jj++) {
            int j = jc * 16 + jj;
            float sig = 1.f / (1.f + __expf(-(dmg[jj] + bdm)));
            float logit = bond[jj] + bb - 10.f * sig;
            if (t0 + tq - 63 + j < 0) logit = -CUDART_INF_F;
            sm.Wt[tq][j] = logit;
        }
    }
    __syncthreads();

    // ---- softmax per t (threads 0..63) ----
    if (tid < 64) {
        float mx = -CUDART_INF_F;
#pragma unroll
        for (int j = 0; j < 64; j++) mx = fmaxf(mx, sm.Wt[tid][j]);
        float s = 0.f;
#pragma unroll
        for (int j = 0; j < 64; j++) {
            float e = __expf(sm.Wt[tid][j] - mx);
            sm.Wt[tid][j] = e;
            s += e;
        }
        float inv = 1.f / s;
#pragma unroll
        for (int j = 0; j < 64; j++) sm.Wt[tid][j] *= inv;
    }
    __syncthreads();

    // ---- AV: warp w handles t in {8w..8w+7}, lane covers e-pair ----
    const int wrp = tid >> 5;
    const int l = tid & 31;
    const int b = bh >> 4;       // bh = b*NH + h
    const int h = bh & (NH - 1);

    for (int q = 0; q < 8; q++) {
        int t = wrp * 8 + q;
        unsigned long long acc = 0ULL;
#pragma unroll
        for (int j = 0; j < 64; j += 4) {
            float4 wv = *(const float4*)&sm.Wt[t][j];
            fma2(acc, pack2(wv.x, wv.x),
                 *(const unsigned long long*)&sm.Vs[t + j + 0][2 * l]);
            fma2(acc, pack2(wv.y, wv.y),
                 *(const unsigned long long*)&sm.Vs[t + j + 1][2 * l]);
            fma2(acc, pack2(wv.z, wv.z),
                 *(const unsigned long long*)&sm.Vs[t + j + 2][2 * l]);
            fma2(acc, pack2(wv.w, wv.w),
                 *(const unsigned long long*)&sm.Vs[t + j + 3][2 * l]);
        }
        float2 o;
        unpack2(acc, o.x, o.y);
        *(float2*)(g_y + ((size_t)(b * Tt + t0 + t)) * Cc + h * HS + 2 * l) = o;
    }
}

// ---------------------------------------------------------------------------
// Launch
// ---------------------------------------------------------------------------
extern "C" void kernel_launch(void* const* d_in, const int* in_sizes, int n_in,
                              void* d_out, int out_size)
{
    const float* x       = (const float*)d_in[0];
    const float* W_disp  = (const float*)d_in[1];
    const float* b_disp  = (const float*)d_in[2];
    const float* W_val   = (const float*)d_in[3];
    const float* b_val   = (const float*)d_in[4];
    const float* rel     = (const float*)d_in[5];
    const float* W_fused = (const float*)d_in[6];
    const float* b_fused = (const float*)d_in[7];
    const float* W_pos   = (const float*)d_in[8];
    const float* W_bond  = (const float*)d_in[9];
    const float* b_bond  = (const float*)d_in[10];
    const float* W_dmg   = (const float*)d_in[11];
    const float* b_dmg   = (const float*)d_in[12];
    const float* W_cproj = (const float*)d_in[13];
    const float* b_cproj = (const float*)d_in[14];
    float* out = (float*)d_out;

    const int M = Bb * Tt;   // 2048
    const int K = Cc;        // 1024

    dim3 gd(M / GBM, (NH * BD) / GBN);   // 16 x 4
    gemm_kernel<0><<<gd, 256>>>(x, W_disp, b_disp, nullptr, M, NH * BD, K);

    dim3 gv(M / GBM, Cc / GBN);          // 16 x 16
    gemm_kernel<1><<<gv, 256>>>(x, W_val, b_val, nullptr, M, Cc, K);

    posfeat_kernel<<<1, DELTA * BD>>>(rel, W_pos);

    qproj_kernel<<<(Bb * NH * Tt) / 256, 256>>>(W_fused);

    cudaFuncSetAttribute(attn_kernel, cudaFuncAttributeMaxDynamicSharedMemorySize,
                         (int)sizeof(AttnSmem));
    attn_kernel<<<Bb * NH * (Tt / DELTA), 256, sizeof(AttnSmem)>>>(
        b_fused, W_bond, b_bond, W_dmg, b_dmg);

    dim3 gc(M / GBM, Cc / GBN);          // 16 x 16
    gemm_kernel<2><<<gc, 256>>>(nullptr, W_cproj, b_cproj, out, M, Cc, K);
}

// round 8
// speedup vs baseline: 2.2789x; 1.6430x over previous
#include <cuda_runtime.h>
#include <cuda_bf16.h>
#include <math_constants.h>
#include <cstddef>
#include <cstdint>

// Problem constants
#define Bb 2
#define Tt 1024
#define Cc 1024
#define NH 16
#define HS 64
#define BD 16
#define DELTA 64

// ---------------------------------------------------------------------------
// Scratch (device globals; no allocation allowed)
// ---------------------------------------------------------------------------
__device__ float g_disp[(size_t)Bb * NH * Tt * BD];   // (B,NH,T,BD)
__device__ float g_val [(size_t)Bb * NH * Tt * HS];   // (B,NH,T,HS)
__device__ float g_Q   [(size_t)Bb * NH * Tt * 32];   // (B,NH,T,32)
__device__ float g_y   [(size_t)Bb * Tt * Cc];        // (B,T,C)
__device__ float g_pos [DELTA * BD];                  // (64,16)

// Split-bf16 operands
__device__ __nv_bfloat16 g_xh [(size_t)Bb * Tt * Cc];
__device__ __nv_bfloat16 g_xl [(size_t)Bb * Tt * Cc];
__device__ __nv_bfloat16 g_wdh[(size_t)NH * BD * Cc];
__device__ __nv_bfloat16 g_wdl[(size_t)NH * BD * Cc];
__device__ __nv_bfloat16 g_wvh[(size_t)Cc * Cc];
__device__ __nv_bfloat16 g_wvl[(size_t)Cc * Cc];
__device__ __nv_bfloat16 g_wch[(size_t)Cc * Cc];
__device__ __nv_bfloat16 g_wcl[(size_t)Cc * Cc];
__device__ __nv_bfloat16 g_yh [(size_t)Bb * Tt * Cc];
__device__ __nv_bfloat16 g_yl [(size_t)Bb * Tt * Cc];

// ---------------------------------------------------------------------------
// Packed f32x2 helpers (attention AV)
// ---------------------------------------------------------------------------
__device__ __forceinline__ unsigned long long pack2(float lo, float hi) {
    unsigned long long r;
    asm("mov.b64 %0, {%1, %2};" : "=l"(r) : "f"(lo), "f"(hi));
    return r;
}
__device__ __forceinline__ void unpack2(unsigned long long v, float& lo, float& hi) {
    asm("mov.b64 {%0, %1}, %2;" : "=f"(lo), "=f"(hi) : "l"(v));
}
__device__ __forceinline__ void fma2(unsigned long long& acc,
                                     unsigned long long a, unsigned long long b) {
    asm("fma.rn.f32x2 %0, %1, %2, %0;" : "+l"(acc) : "l"(a), "l"(b));
}

// ---------------------------------------------------------------------------
// mma.sync helpers (sm_80+ baseline PTX; works on plain sm_103 target)
// ---------------------------------------------------------------------------
__device__ __forceinline__ uint32_t smem_u32(const void* p) {
    uint32_t a;
    asm("{ .reg .u64 t; cvta.to.shared.u64 t, %1; cvt.u32.u64 %0, t; }"
        : "=r"(a) : "l"(p));
    return a;
}
__device__ __forceinline__ void ldsm_x4(uint32_t& r0, uint32_t& r1,
                                        uint32_t& r2, uint32_t& r3, uint32_t addr) {
    asm volatile("ldmatrix.sync.aligned.m8n8.x4.shared.b16 {%0,%1,%2,%3}, [%4];"
                 : "=r"(r0), "=r"(r1), "=r"(r2), "=r"(r3) : "r"(addr));
}
__device__ __forceinline__ void mma_bf16(float* c, const uint32_t* a,
                                         uint32_t b0, uint32_t b1) {
    asm volatile(
        "mma.sync.aligned.m16n8k16.row.col.f32.bf16.bf16.f32 "
        "{%0,%1,%2,%3}, {%4,%5,%6,%7}, {%8,%9}, {%0,%1,%2,%3};"
        : "+f"(c[0]), "+f"(c[1]), "+f"(c[2]), "+f"(c[3])
        : "r"(a[0]), "r"(a[1]), "r"(a[2]), "r"(a[3]), "r"(b0), "r"(b1));
}

// ---------------------------------------------------------------------------
// Split fp32 -> bf16 hi + bf16 lo (2 elements/thread)
// ---------------------------------------------------------------------------
__global__ __launch_bounds__(256) void split_kernel(
    const float* __restrict__ src,
    __nv_bfloat16* __restrict__ hi, __nv_bfloat16* __restrict__ lo)
{
    int i = blockIdx.x * 256 + threadIdx.x;
    float2 v = ((const float2*)src)[i];
    __nv_bfloat16 h0 = __float2bfloat16(v.x);
    __nv_bfloat16 h1 = __float2bfloat16(v.y);
    __nv_bfloat16 l0 = __float2bfloat16(v.x - __bfloat162float(h0));
    __nv_bfloat16 l1 = __float2bfloat16(v.y - __bfloat162float(h1));
    __nv_bfloat162 hv; hv.x = h0; hv.y = h1;
    __nv_bfloat162 lv; lv.x = l0; lv.y = l1;
    ((__nv_bfloat162*)hi)[i] = hv;
    ((__nv_bfloat162*)lo)[i] = lv;
}

// ---------------------------------------------------------------------------
// Split-bf16 tensor-core GEMM via mma.sync:
//   C[m,n] = bias[n] + sum_k A[m,k]*W[n,k],  acc = AhBh + AhBl + AlBh (fp32)
// Tile BM=128 x BN=64 x BK=32. 256 threads = 8 warps (4 m x 2 n), each warp
// owns a 32x32 output (2 x 4 m16n8 fragments).
// Smem row stride 40 bf16 (80B) -> conflict-free ldmatrix.
// MODE 0: scatter to g_disp; MODE 1: scatter to g_val; MODE 2: plain -> Cout.
// ---------------------------------------------------------------------------
#define MT 128
#define NT 64
#define KB 32
#define RS 40   // smem row stride in bf16 elements

template<int MODE>
__global__ __launch_bounds__(256)
void mma_gemm(const __nv_bfloat16* __restrict__ Ah, const __nv_bfloat16* __restrict__ Al,
              const __nv_bfloat16* __restrict__ Bh, const __nv_bfloat16* __restrict__ Bl,
              const float* __restrict__ bias, float* __restrict__ Cout,
              int M, int N, int K)
{
    __shared__ __nv_bfloat16 sAh[MT * RS];
    __shared__ __nv_bfloat16 sAl[MT * RS];
    __shared__ __nv_bfloat16 sBh[NT * RS];
    __shared__ __nv_bfloat16 sBl[NT * RS];

    const int tid = threadIdx.x;
    const int wid = tid >> 5, lane = tid & 31;
    const int wm = wid & 3;          // m32 block within tile
    const int wn = wid >> 2;         // n32 block within tile
    const int bm = blockIdx.x * MT;
    const int bn = blockIdx.y * NT;

    float acc[2][4][4];
#pragma unroll
    for (int mi = 0; mi < 2; mi++)
#pragma unroll
        for (int ni = 0; ni < 4; ni++)
#pragma unroll
            for (int q = 0; q < 4; q++) acc[mi][ni][q] = 0.f;

    // ldmatrix base addresses (byte offsets within row handled per kst)
    const uint32_t aAh = smem_u32(sAh), aAl = smem_u32(sAl);
    const uint32_t aBh = smem_u32(sBh), aBl = smem_u32(sBl);
    // A: row = wm*32 + mi*16 + (lane&15), col = kst*16 + (lane>>4)*8
    const int a_row_in = (lane & 15);
    const int a_col8 = (lane >> 4) * 8;
    // B: row = wn*32 + ng*16 + ((lane>>4)<<3) + (lane&7), col = kst*16 + ((lane>>3)&1)*8
    const int b_row_in = ((lane >> 4) << 3) + (lane & 7);
    const int b_col8 = ((lane >> 3) & 1) * 8;

    for (int k0 = 0; k0 < K; k0 += KB) {
        // ---- load tiles (uint4 = 8 bf16) ----
#pragma unroll
        for (int t = 0; t < 2; t++) {
            int i = tid + t * 256;             // 512 uint4 per A tile
            int row = i >> 2, q = i & 3;
            size_t go = (size_t)(bm + row) * K + k0 + q * 8;
            int so = row * RS + q * 8;
            *(uint4*)(sAh + so) = *(const uint4*)(Ah + go);
            *(uint4*)(sAl + so) = *(const uint4*)(Al + go);
        }
        {
            int row = tid >> 2, q = tid & 3;   // 256 uint4 per B tile
            size_t go = (size_t)(bn + row) * K + k0 + q * 8;
            int so = row * RS + q * 8;
            *(uint4*)(sBh + so) = *(const uint4*)(Bh + go);
            *(uint4*)(sBl + so) = *(const uint4*)(Bl + go);
        }
        __syncthreads();

        // ---- compute: 2 k16-steps ----
#pragma unroll
        for (int kst = 0; kst < 2; kst++) {
            const int kc = kst * 16;
            uint32_t ah[2][4], al[2][4];
#pragma unroll
            for (int mi = 0; mi < 2; mi++) {
                int off = ((wm * 32 + mi * 16 + a_row_in) * RS + kc + a_col8) * 2;
                ldsm_x4(ah[mi][0], ah[mi][1], ah[mi][2], ah[mi][3], aAh + off);
                ldsm_x4(al[mi][0], al[mi][1], al[mi][2], al[mi][3], aAl + off);
            }
            uint32_t bh[4][2], bl[4][2];
#pragma unroll
            for (int ng = 0; ng < 2; ng++) {
                int off = ((wn * 32 + ng * 16 + b_row_in) * RS + kc + b_col8) * 2;
                uint32_t r0, r1, r2, r3;
                ldsm_x4(r0, r1, r2, r3, aBh + off);
                bh[ng * 2 + 0][0] = r0; bh[ng * 2 + 0][1] = r1;
                bh[ng * 2 + 1][0] = r2; bh[ng * 2 + 1][1] = r3;
                ldsm_x4(r0, r1, r2, r3, aBl + off);
                bl[ng * 2 + 0][0] = r0; bl[ng * 2 + 0][1] = r1;
                bl[ng * 2 + 1][0] = r2; bl[ng * 2 + 1][1] = r3;
            }
#pragma unroll
            for (int mi = 0; mi < 2; mi++)
#pragma unroll
                for (int ni = 0; ni < 4; ni++) {
                    mma_bf16(acc[mi][ni], ah[mi], bh[ni][0], bh[ni][1]);
                    mma_bf16(acc[mi][ni], ah[mi], bl[ni][0], bl[ni][1]);
                    mma_bf16(acc[mi][ni], al[mi], bh[ni][0], bh[ni][1]);
                }
        }
        __syncthreads();
    }

    // ---- epilogue: fragment -> global (float2 per reg pair) ----
    const int gr = lane >> 2;        // group row 0..7
    const int gc = (lane & 3) * 2;   // col pair base
#pragma unroll
    for (int mi = 0; mi < 2; mi++) {
#pragma unroll
        for (int ni = 0; ni < 4; ni++) {
            int n = bn + wn * 32 + ni * 8 + gc;
            float bx = bias[n], by = bias[n + 1];
#pragma unroll
            for (int half = 0; half < 2; half++) {
                int m = bm + wm * 32 + mi * 16 + gr + half * 8;
                float vx = acc[mi][ni][half * 2 + 0] + bx;
                float vy = acc[mi][ni][half * 2 + 1] + by;
                if (MODE == 0) {
                    int b = m >> 10, t = m & (Tt - 1);
                    int h = n >> 4, d = n & (BD - 1);
                    float2 o; o.x = vx; o.y = vy;
                    *(float2*)(g_disp + ((size_t)((b * NH + h) * Tt + t)) * BD + d) = o;
                } else if (MODE == 1) {
                    int b = m >> 10, t = m & (Tt - 1);
                    int h = n >> 6, e = n & (HS - 1);
                    float2 o; o.x = vx; o.y = vy;
                    *(float2*)(g_val + ((size_t)((b * NH + h) * Tt + t)) * HS + e) = o;
                } else {
                    float2 o; o.x = vx; o.y = vy;
                    *(float2*)(Cout + (size_t)m * N + n) = o;
                }
            }
        }
    }
}

// ---------------------------------------------------------------------------
// pos_feat[j,k] = sum_e rel[j,e] * W_pos[k,e]   (64x16)
// ---------------------------------------------------------------------------
__global__ void posfeat_kernel(const float* __restrict__ rel,
                               const float* __restrict__ Wpos)
{
    int i = threadIdx.x;
    int j = i >> 4, k = i & 15;
    float s = 0.f;
#pragma unroll
    for (int e = 0; e < BD; e++) s += rel[j * BD + e] * Wpos[k * BD + e];
    g_pos[j * BD + k] = s;
}

// ---------------------------------------------------------------------------
// qproj: g_Q[token][o] = sum_d W_fused[o][d] * g_disp[token][d]
// ---------------------------------------------------------------------------
__global__ __launch_bounds__(256) void qproj_kernel(const float* __restrict__ Wf)
{
    __shared__ float Wfs[32 * BD];
    int tid = threadIdx.x;
    for (int i = tid; i < 32 * BD; i += 256) Wfs[i] = Wf[i];
    __syncthreads();

    size_t token = (size_t)blockIdx.x * 256 + tid;
    float d[BD];
    const float4* dp = (const float4*)(g_disp + token * BD);
#pragma unroll
    for (int q = 0; q < 4; q++) {
        float4 v = dp[q];
        d[q * 4 + 0] = v.x; d[q * 4 + 1] = v.y;
        d[q * 4 + 2] = v.z; d[q * 4 + 3] = v.w;
    }
    float* qout = g_Q + token * 32;
#pragma unroll
    for (int o4 = 0; o4 < 8; o4++) {
        float4 r;
        float s0 = 0.f, s1 = 0.f, s2 = 0.f, s3 = 0.f;
#pragma unroll
        for (int dd = 0; dd < BD; dd++) {
            s0 += Wfs[(o4 * 4 + 0) * BD + dd] * d[dd];
            s1 += Wfs[(o4 * 4 + 1) * BD + dd] * d[dd];
            s2 += Wfs[(o4 * 4 + 2) * BD + dd] * d[dd];
            s3 += Wfs[(o4 * 4 + 3) * BD + dd] * d[dd];
        }
        r.x = s0; r.y = s1; r.z = s2; r.w = s3;
        *(float4*)(qout + o4 * 4) = r;
    }
}

// ---------------------------------------------------------------------------
// Attention: one block (256 threads) per (b,h, 64-wide t-tile).
// ---------------------------------------------------------------------------
struct AttnSmem {
    float QsT[32][132];
    float posB[16][64];
    float Wbs[16];
    float Wds[16];
    float Vs[127][64];
    float Wt[64][68];
};

__device__ __forceinline__ float gelu_t(float z) {
    float arg = z * (0.7978845608f + 0.0356774081f * z * z);
    float th;
    asm("tanh.approx.f32 %0, %1;" : "=f"(th) : "f"(arg));
    return 0.5f * z * (1.f + th);
}

__global__ __launch_bounds__(256) void attn_kernel(
    const float* __restrict__ b_fused,
    const float* __restrict__ W_bond, const float* __restrict__ b_bond,
    const float* __restrict__ W_dmg,  const float* __restrict__ b_dmg)
{
    extern __shared__ char smraw[];
    AttnSmem& sm = *reinterpret_cast<AttnSmem*>(smraw);

    const int bid = blockIdx.x;
    const int tile = bid & 15;
    const int bh = bid >> 4;
    const int t0 = tile * 64;
    const int tid = threadIdx.x;

    const float* __restrict__ Qbase = g_Q + (size_t)bh * Tt * 32;
    const float* __restrict__ Vbase = g_val + (size_t)bh * Tt * HS;

    for (int i = tid; i < 127 * 8; i += 256) {
        int r = i >> 3, kq = (i & 7) << 2;
        int tp = t0 - 63 + r;
        float4 v = make_float4(0.f, 0.f, 0.f, 0.f);
        if (tp >= 0) v = *(const float4*)(Qbase + (size_t)tp * 32 + kq);
        sm.QsT[kq + 0][r] = v.x; sm.QsT[kq + 1][r] = v.y;
        sm.QsT[kq + 2][r] = v.z; sm.QsT[kq + 3][r] = v.w;
    }
    for (int i = tid; i < 16 * 64; i += 256) {
        int k = i >> 6, j = i & 63;
        sm.posB[k][j] = g_pos[j * BD + k] + b_fused[k];
    }
    if (tid < 16) { sm.Wbs[tid] = W_bond[tid]; sm.Wds[tid] = W_dmg[tid]; }
    for (int i = tid; i < 127 * 16; i += 256) {
        int r = i >> 4, eq = (i & 15) << 2;
        int tp = t0 - 63 + r;
        float4 v = make_float4(0.f, 0.f, 0.f, 0.f);
        if (tp >= 0) v = *(const float4*)(Vbase + (size_t)tp * HS + eq);
        *(float4*)&sm.Vs[r][eq] = v;
    }
    __syncthreads();

    const int tq = tid & 63;
    const int jc = tid >> 6;
    const int c = tq + 63;

    float bond[16], dmg[16];
#pragma unroll
    for (int jj = 0; jj < 16; jj++) { bond[jj] = 0.f; dmg[jj] = 0.f; }

#pragma unroll
    for (int k = 0; k < 16; k++) {
        float qbc = sm.QsT[k][c];
        float qdc = sm.QsT[16 + k][c] - b_fused[16 + k];
        float wb = sm.Wbs[k];
        float wd = sm.Wds[k];
#pragma unroll
        for (int jj = 0; jj < 16; jj++) {
            int j = jc * 16 + jj;
            int r = tq + j;
            float db = sm.QsT[k][r] - qbc + sm.posB[k][j];
            float dd = sm.QsT[16 + k][r] - qdc;
            bond[jj] += gelu_t(db) * wb;
            dmg[jj]  += gelu_t(dd) * wd;
        }
    }
    {
        float bb = b_bond[0];
        float bdm = b_dmg[0];
#pragma unroll
        for (int jj = 0; jj < 16; jj++) {
            int j = jc * 16 + jj;
            float sig = 1.f / (1.f + __expf(-(dmg[jj] + bdm)));
            float logit = bond[jj] + bb - 10.f * sig;
            if (t0 + tq - 63 + j < 0) logit = -CUDART_INF_F;
            sm.Wt[tq][j] = logit;
        }
    }
    __syncthreads();

    if (tid < 64) {
        float mx = -CUDART_INF_F;
#pragma unroll
        for (int j = 0; j < 64; j++) mx = fmaxf(mx, sm.Wt[tid][j]);
        float s = 0.f;
#pragma unroll
        for (int j = 0; j < 64; j++) {
            float e = __expf(sm.Wt[tid][j] - mx);
            sm.Wt[tid][j] = e;
            s += e;
        }
        float inv = 1.f / s;
#pragma unroll
        for (int j = 0; j < 64; j++) sm.Wt[tid][j] *= inv;
    }
    __syncthreads();

    const int wrp = tid >> 5;
    const int l = tid & 31;
    const int b = bh >> 4;
    const int h = bh & (NH - 1);

    for (int q = 0; q < 8; q++) {
        int t = wrp * 8 + q;
        unsigned long long acc = 0ULL;
#pragma unroll
        for (int j = 0; j < 64; j += 4) {
            float4 wv = *(const float4*)&sm.Wt[t][j];
            fma2(acc, pack2(wv.x, wv.x),
                 *(const unsigned long long*)&sm.Vs[t + j + 0][2 * l]);
            fma2(acc, pack2(wv.y, wv.y),
                 *(const unsigned long long*)&sm.Vs[t + j + 1][2 * l]);
            fma2(acc, pack2(wv.z, wv.z),
                 *(const unsigned long long*)&sm.Vs[t + j + 2][2 * l]);
            fma2(acc, pack2(wv.w, wv.w),
                 *(const unsigned long long*)&sm.Vs[t + j + 3][2 * l]);
        }
        float2 o;
        unpack2(acc, o.x, o.y);
        *(float2*)(g_y + ((size_t)(b * Tt + t0 + t)) * Cc + h * HS + 2 * l) = o;
    }
}

// ---------------------------------------------------------------------------
// Launch
// ---------------------------------------------------------------------------
extern "C" void kernel_launch(void* const* d_in, const int* in_sizes, int n_in,
                              void* d_out, int out_size)
{
    const float* x       = (const float*)d_in[0];
    const float* W_disp  = (const float*)d_in[1];
    const float* b_disp  = (const float*)d_in[2];
    const float* W_val   = (const float*)d_in[3];
    const float* b_val   = (const float*)d_in[4];
    const float* rel     = (const float*)d_in[5];
    const float* W_fused = (const float*)d_in[6];
    const float* b_fused = (const float*)d_in[7];
    const float* W_pos   = (const float*)d_in[8];
    const float* W_bond  = (const float*)d_in[9];
    const float* b_bond  = (const float*)d_in[10];
    const float* W_dmg   = (const float*)d_in[11];
    const float* b_dmg   = (const float*)d_in[12];
    const float* W_cproj = (const float*)d_in[13];
    const float* b_cproj = (const float*)d_in[14];
    float* out = (float*)d_out;

    const int M = Bb * Tt;   // 2048
    const int K = Cc;        // 1024

    __nv_bfloat16 *xh, *xl, *wdh, *wdl, *wvh, *wvl, *wch, *wcl, *yh, *yl;
    void* p;
    cudaGetSymbolAddress(&p, g_xh);  xh  = (__nv_bfloat16*)p;
    cudaGetSymbolAddress(&p, g_xl);  xl  = (__nv_bfloat16*)p;
    cudaGetSymbolAddress(&p, g_wdh); wdh = (__nv_bfloat16*)p;
    cudaGetSymbolAddress(&p, g_wdl); wdl = (__nv_bfloat16*)p;
    cudaGetSymbolAddress(&p, g_wvh); wvh = (__nv_bfloat16*)p;
    cudaGetSymbolAddress(&p, g_wvl); wvl = (__nv_bfloat16*)p;
    cudaGetSymbolAddress(&p, g_wch); wch = (__nv_bfloat16*)p;
    cudaGetSymbolAddress(&p, g_wcl); wcl = (__nv_bfloat16*)p;
    cudaGetSymbolAddress(&p, g_yh);  yh  = (__nv_bfloat16*)p;
    cudaGetSymbolAddress(&p, g_yl);  yl  = (__nv_bfloat16*)p;
    void* gy; cudaGetSymbolAddress(&gy, g_y);

    // Splits of GEMM inputs
    split_kernel<<<(M * K / 2) / 256, 256>>>(x, xh, xl);
    split_kernel<<<(NH * BD * K / 2) / 256, 256>>>(W_disp, wdh, wdl);
    split_kernel<<<(K * K / 2) / 256, 256>>>(W_val, wvh, wvl);
    split_kernel<<<(K * K / 2) / 256, 256>>>(W_cproj, wch, wcl);

    dim3 gd(M / MT, (NH * BD) / NT);   // 16 x 4
    mma_gemm<0><<<gd, 256>>>(xh, xl, wdh, wdl, b_disp, nullptr, M, NH * BD, K);

    dim3 gv(M / MT, Cc / NT);          // 16 x 16
    mma_gemm<1><<<gv, 256>>>(xh, xl, wvh, wvl, b_val, nullptr, M, Cc, K);

    posfeat_kernel<<<1, DELTA * BD>>>(rel, W_pos);
    qproj_kernel<<<(Bb * NH * Tt) / 256, 256>>>(W_fused);

    cudaFuncSetAttribute(attn_kernel, cudaFuncAttributeMaxDynamicSharedMemorySize,
                         (int)sizeof(AttnSmem));
    attn_kernel<<<Bb * NH * (Tt / DELTA), 256, sizeof(AttnSmem)>>>(
        b_fused, W_bond, b_bond, W_dmg, b_dmg);

    split_kernel<<<(M * K / 2) / 256, 256>>>((const float*)gy, yh, yl);

    dim3 gc(M / MT, Cc / NT);          // 16 x 16
    mma_gemm<2><<<gc, 256>>>(yh, yl, wch, wcl, b_cproj, out, M, Cc, K);
}

// round 9
// speedup vs baseline: 2.4756x; 1.0863x over previous
#include <cuda_runtime.h>
#include <cuda_bf16.h>
#include <math_constants.h>
#include <cstddef>
#include <cstdint>

// Problem constants
#define Bb 2
#define Tt 1024
#define Cc 1024
#define NH 16
#define HS 64
#define BD 16
#define DELTA 64

// ---------------------------------------------------------------------------
// Scratch (device globals; no allocation allowed)
// ---------------------------------------------------------------------------
__device__ float g_disp[(size_t)Bb * NH * Tt * BD];   // (B,NH,T,BD)
__device__ float g_val [(size_t)Bb * NH * Tt * HS];   // (B,NH,T,HS)
__device__ float g_Q   [(size_t)Bb * NH * Tt * 32];   // (B,NH,T,32)
__device__ float g_pos [DELTA * BD];                  // (64,16)

// Split-bf16 operands
__device__ __nv_bfloat16 g_xh [(size_t)Bb * Tt * Cc];
__device__ __nv_bfloat16 g_xl [(size_t)Bb * Tt * Cc];
__device__ __nv_bfloat16 g_wdh[(size_t)NH * BD * Cc];
__device__ __nv_bfloat16 g_wdl[(size_t)NH * BD * Cc];
__device__ __nv_bfloat16 g_wvh[(size_t)Cc * Cc];
__device__ __nv_bfloat16 g_wvl[(size_t)Cc * Cc];
__device__ __nv_bfloat16 g_wch[(size_t)Cc * Cc];
__device__ __nv_bfloat16 g_wcl[(size_t)Cc * Cc];
__device__ __nv_bfloat16 g_yh [(size_t)Bb * Tt * Cc];
__device__ __nv_bfloat16 g_yl [(size_t)Bb * Tt * Cc];

// ---------------------------------------------------------------------------
// Packed f32x2 helpers
// ---------------------------------------------------------------------------
__device__ __forceinline__ unsigned long long pack2(float lo, float hi) {
    unsigned long long r;
    asm("mov.b64 %0, {%1, %2};" : "=l"(r) : "f"(lo), "f"(hi));
    return r;
}
__device__ __forceinline__ void unpack2(unsigned long long v, float& lo, float& hi) {
    asm("mov.b64 {%0, %1}, %2;" : "=f"(lo), "=f"(hi) : "l"(v));
}
__device__ __forceinline__ void fma2(unsigned long long& acc,
                                     unsigned long long a, unsigned long long b) {
    asm("fma.rn.f32x2 %0, %1, %2, %0;" : "+l"(acc) : "l"(a), "l"(b));
}

// ---------------------------------------------------------------------------
// mma.sync / ldmatrix / cp.async helpers (sm_80+ baseline PTX)
// ---------------------------------------------------------------------------
__device__ __forceinline__ uint32_t smem_u32(const void* p) {
    uint32_t a;
    asm("{ .reg .u64 t; cvta.to.shared.u64 t, %1; cvt.u32.u64 %0, t; }"
        : "=r"(a) : "l"(p));
    return a;
}
__device__ __forceinline__ void ldsm_x4(uint32_t& r0, uint32_t& r1,
                                        uint32_t& r2, uint32_t& r3, uint32_t addr) {
    asm volatile("ldmatrix.sync.aligned.m8n8.x4.shared.b16 {%0,%1,%2,%3}, [%4];"
                 : "=r"(r0), "=r"(r1), "=r"(r2), "=r"(r3) : "r"(addr));
}
__device__ __forceinline__ void mma_bf16(float* c, const uint32_t* a,
                                         uint32_t b0, uint32_t b1) {
    asm volatile(
        "mma.sync.aligned.m16n8k16.row.col.f32.bf16.bf16.f32 "
        "{%0,%1,%2,%3}, {%4,%5,%6,%7}, {%8,%9}, {%0,%1,%2,%3};"
        : "+f"(c[0]), "+f"(c[1]), "+f"(c[2]), "+f"(c[3])
        : "r"(a[0]), "r"(a[1]), "r"(a[2]), "r"(a[3]), "r"(b0), "r"(b1));
}
__device__ __forceinline__ void cp16(uint32_t saddr, const void* gptr) {
    asm volatile("cp.async.cg.shared.global [%0], [%1], 16;"
                 :: "r"(saddr), "l"(gptr));
}
#define CP_COMMIT() asm volatile("cp.async.commit_group;" ::: "memory")
#define CP_WAIT(n)  asm volatile("cp.async.wait_group %0;" :: "n"(n) : "memory")

// ---------------------------------------------------------------------------
// Split fp32 -> bf16 hi + bf16 lo (2 elements/thread)
// ---------------------------------------------------------------------------
__global__ __launch_bounds__(256) void split_kernel(
    const float* __restrict__ src,
    __nv_bfloat16* __restrict__ hi, __nv_bfloat16* __restrict__ lo)
{
    int i = blockIdx.x * 256 + threadIdx.x;
    float2 v = ((const float2*)src)[i];
    __nv_bfloat16 h0 = __float2bfloat16(v.x);
    __nv_bfloat16 h1 = __float2bfloat16(v.y);
    __nv_bfloat16 l0 = __float2bfloat16(v.x - __bfloat162float(h0));
    __nv_bfloat16 l1 = __float2bfloat16(v.y - __bfloat162float(h1));
    __nv_bfloat162 hv; hv.x = h0; hv.y = h1;
    __nv_bfloat162 lv; lv.x = l0; lv.y = l1;
    ((__nv_bfloat162*)hi)[i] = hv;
    ((__nv_bfloat162*)lo)[i] = lv;
}

// ---------------------------------------------------------------------------
// disp GEMM (small N): split-bf16 mma.sync, BM=128 x BN=64 x BK=32,
// 8 warps (4m x 2n), warp tile 32x32. Single-buffered (proven correct R8).
// ---------------------------------------------------------------------------
#define MT 128
#define NT 64
#define KB 32
#define RS 40   // smem row stride in bf16 elements

__global__ __launch_bounds__(256)
void mma_gemm_disp(const __nv_bfloat16* __restrict__ Ah, const __nv_bfloat16* __restrict__ Al,
                   const __nv_bfloat16* __restrict__ Bh, const __nv_bfloat16* __restrict__ Bl,
                   const float* __restrict__ bias, int M, int N, int K)
{
    __shared__ __nv_bfloat16 sAh[MT * RS];
    __shared__ __nv_bfloat16 sAl[MT * RS];
    __shared__ __nv_bfloat16 sBh[NT * RS];
    __shared__ __nv_bfloat16 sBl[NT * RS];

    const int tid = threadIdx.x;
    const int wid = tid >> 5, lane = tid & 31;
    const int wm = wid & 3;
    const int wn = wid >> 2;
    const int bm = blockIdx.x * MT;
    const int bn = blockIdx.y * NT;

    float acc[2][4][4];
#pragma unroll
    for (int mi = 0; mi < 2; mi++)
#pragma unroll
        for (int ni = 0; ni < 4; ni++)
#pragma unroll
            for (int q = 0; q < 4; q++) acc[mi][ni][q] = 0.f;

    const uint32_t aAh = smem_u32(sAh), aAl = smem_u32(sAl);
    const uint32_t aBh = smem_u32(sBh), aBl = smem_u32(sBl);
    const int a_row_in = (lane & 15);
    const int a_col8 = (lane >> 4) * 8;
    const int b_row_in = ((lane >> 4) << 3) + (lane & 7);
    const int b_col8 = ((lane >> 3) & 1) * 8;

    for (int k0 = 0; k0 < K; k0 += KB) {
#pragma unroll
        for (int t = 0; t < 2; t++) {
            int i = tid + t * 256;
            int row = i >> 2, q = i & 3;
            size_t go = (size_t)(bm + row) * K + k0 + q * 8;
            int so = row * RS + q * 8;
            *(uint4*)(sAh + so) = *(const uint4*)(Ah + go);
            *(uint4*)(sAl + so) = *(const uint4*)(Al + go);
        }
        {
            int row = tid >> 2, q = tid & 3;
            size_t go = (size_t)(bn + row) * K + k0 + q * 8;
            int so = row * RS + q * 8;
            *(uint4*)(sBh + so) = *(const uint4*)(Bh + go);
            *(uint4*)(sBl + so) = *(const uint4*)(Bl + go);
        }
        __syncthreads();

#pragma unroll
        for (int kst = 0; kst < 2; kst++) {
            const int kc = kst * 16;
            uint32_t ah[2][4], al[2][4];
#pragma unroll
            for (int mi = 0; mi < 2; mi++) {
                int off = ((wm * 32 + mi * 16 + a_row_in) * RS + kc + a_col8) * 2;
                ldsm_x4(ah[mi][0], ah[mi][1], ah[mi][2], ah[mi][3], aAh + off);
                ldsm_x4(al[mi][0], al[mi][1], al[mi][2], al[mi][3], aAl + off);
            }
            uint32_t bh[4][2], bl[4][2];
#pragma unroll
            for (int ng = 0; ng < 2; ng++) {
                int off = ((wn * 32 + ng * 16 + b_row_in) * RS + kc + b_col8) * 2;
                uint32_t r0, r1, r2, r3;
                ldsm_x4(r0, r1, r2, r3, aBh + off);
                bh[ng * 2 + 0][0] = r0; bh[ng * 2 + 0][1] = r1;
                bh[ng * 2 + 1][0] = r2; bh[ng * 2 + 1][1] = r3;
                ldsm_x4(r0, r1, r2, r3, aBl + off);
                bl[ng * 2 + 0][0] = r0; bl[ng * 2 + 0][1] = r1;
                bl[ng * 2 + 1][0] = r2; bl[ng * 2 + 1][1] = r3;
            }
#pragma unroll
            for (int mi = 0; mi < 2; mi++)
#pragma unroll
                for (int ni = 0; ni < 4; ni++) {
                    mma_bf16(acc[mi][ni], ah[mi], bh[ni][0], bh[ni][1]);
                    mma_bf16(acc[mi][ni], ah[mi], bl[ni][0], bl[ni][1]);
                    mma_bf16(acc[mi][ni], al[mi], bh[ni][0], bh[ni][1]);
                }
        }
        __syncthreads();
    }

    const int gr = lane >> 2;
    const int gc = (lane & 3) * 2;
#pragma unroll
    for (int mi = 0; mi < 2; mi++) {
#pragma unroll
        for (int ni = 0; ni < 4; ni++) {
            int n = bn + wn * 32 + ni * 8 + gc;
            float bx = bias[n], by = bias[n + 1];
#pragma unroll
            for (int half = 0; half < 2; half++) {
                int m = bm + wm * 32 + mi * 16 + gr + half * 8;
                float vx = acc[mi][ni][half * 2 + 0] + bx;
                float vy = acc[mi][ni][half * 2 + 1] + by;
                int b = m >> 10, t = m & (Tt - 1);
                int h = n >> 4, d = n & (BD - 1);
                float2 o; o.x = vx; o.y = vy;
                *(float2*)(g_disp + ((size_t)((b * NH + h) * Tt + t)) * BD + d) = o;
            }
        }
    }
}

// ---------------------------------------------------------------------------
// Big GEMM: BM=128 x BN=128 x BK=32, cp.async double-buffered.
// 8 warps (4m x 2n), warp tile 32x64 (2 x 8 m16n8 fragments).
// MODE 1: scatter to g_val; MODE 2: plain -> Cout.
// Dynamic smem: 2 stages x (Ah|Al: 128xRS, Bh|Bl: 128xRS) bf16 = 81920 B.
// ---------------------------------------------------------------------------
#define NT2 128
#define STAGE_ELEMS (4 * 128 * RS)              // bf16 per stage = 20480

template<int MODE>
__global__ __launch_bounds__(256)
void mma_gemm_big(const __nv_bfloat16* __restrict__ Ah, const __nv_bfloat16* __restrict__ Al,
                  const __nv_bfloat16* __restrict__ Bh, const __nv_bfloat16* __restrict__ Bl,
                  const float* __restrict__ bias, float* __restrict__ Cout,
                  int M, int N, int K)
{
    extern __shared__ __nv_bfloat16 smem[];

    const int tid = threadIdx.x;
    const int wid = tid >> 5, lane = tid & 31;
    const int wm = wid & 3;          // 32-row group
    const int wn = wid >> 2;         // 64-col group
    const int bm = blockIdx.x * MT;
    const int bn = blockIdx.y * NT2;

    float acc[2][8][4];
#pragma unroll
    for (int mi = 0; mi < 2; mi++)
#pragma unroll
        for (int ni = 0; ni < 8; ni++)
#pragma unroll
            for (int q = 0; q < 4; q++) acc[mi][ni][q] = 0.f;

    const uint32_t sbase = smem_u32(smem);
    // per-stage element offsets
    //   A_h: 0        A_l: 128*RS   B_h: 2*128*RS   B_l: 3*128*RS
    const int a_row_in = (lane & 15);
    const int a_col8 = (lane >> 4) * 8;
    const int b_row_in = ((lane >> 4) << 3) + (lane & 7);
    const int b_col8 = ((lane >> 3) & 1) * 8;

    // load row/col assignment for cp.async (each thread: 2 A-uint4 x2, 2 B-uint4 x2)
    const int l_row = tid >> 2;            // 0..63
    const int l_q = tid & 3;               // 16B quarter

    const int nch = K / KB;

    // ---- stage load helper (macro-ish lambda) ----
    auto load_stage = [&](int stage, int k0) {
        uint32_t sb = sbase + stage * STAGE_ELEMS * 2;
#pragma unroll
        for (int t = 0; t < 2; t++) {
            int row = l_row + t * 64;      // 0..127
            int so = (row * RS + l_q * 8) * 2;
            size_t go = (size_t)(bm + row) * K + k0 + l_q * 8;
            cp16(sb + so, Ah + go);
            cp16(sb + (128 * RS) * 2 + so, Al + go);
        }
#pragma unroll
        for (int t = 0; t < 2; t++) {
            int row = l_row + t * 64;
            int so = (row * RS + l_q * 8) * 2;
            size_t go = (size_t)(bn + row) * K + k0 + l_q * 8;
            cp16(sb + (2 * 128 * RS) * 2 + so, Bh + go);
            cp16(sb + (3 * 128 * RS) * 2 + so, Bl + go);
        }
    };

    load_stage(0, 0);
    CP_COMMIT();

    for (int ch = 0; ch < nch; ch++) {
        const int cur = ch & 1;
        if (ch + 1 < nch) {
            load_stage(cur ^ 1, (ch + 1) * KB);
            CP_COMMIT();
            CP_WAIT(1);
        } else {
            CP_WAIT(0);
        }
        __syncthreads();

        const uint32_t sb = sbase + cur * STAGE_ELEMS * 2;
        const uint32_t aAh = sb;
        const uint32_t aAl = sb + (128 * RS) * 2;
        const uint32_t aBh = sb + (2 * 128 * RS) * 2;
        const uint32_t aBl = sb + (3 * 128 * RS) * 2;

#pragma unroll
        for (int kst = 0; kst < 2; kst++) {
            const int kc = kst * 16;
            uint32_t ah[2][4], al[2][4];
#pragma unroll
            for (int mi = 0; mi < 2; mi++) {
                int off = ((wm * 32 + mi * 16 + a_row_in) * RS + kc + a_col8) * 2;
                ldsm_x4(ah[mi][0], ah[mi][1], ah[mi][2], ah[mi][3], aAh + off);
                ldsm_x4(al[mi][0], al[mi][1], al[mi][2], al[mi][3], aAl + off);
            }
            uint32_t bh[8][2], bl[8][2];
#pragma unroll
            for (int ng = 0; ng < 4; ng++) {
                int off = ((wn * 64 + ng * 16 + b_row_in) * RS + kc + b_col8) * 2;
                uint32_t r0, r1, r2, r3;
                ldsm_x4(r0, r1, r2, r3, aBh + off);
                bh[ng * 2 + 0][0] = r0; bh[ng * 2 + 0][1] = r1;
                bh[ng * 2 + 1][0] = r2; bh[ng * 2 + 1][1] = r3;
                ldsm_x4(r0, r1, r2, r3, aBl + off);
                bl[ng * 2 + 0][0] = r0; bl[ng * 2 + 0][1] = r1;
                bl[ng * 2 + 1][0] = r2; bl[ng * 2 + 1][1] = r3;
            }
#pragma unroll
            for (int mi = 0; mi < 2; mi++)
#pragma unroll
                for (int ni = 0; ni < 8; ni++) {
                    mma_bf16(acc[mi][ni], ah[mi], bh[ni][0], bh[ni][1]);
                    mma_bf16(acc[mi][ni], ah[mi], bl[ni][0], bl[ni][1]);
                    mma_bf16(acc[mi][ni], al[mi], bh[ni][0], bh[ni][1]);
                }
        }
        __syncthreads();
    }

    // ---- epilogue ----
    const int gr = lane >> 2;
    const int gc = (lane & 3) * 2;
#pragma unroll
    for (int mi = 0; mi < 2; mi++) {
#pragma unroll
        for (int ni = 0; ni < 8; ni++) {
            int n = bn + wn * 64 + ni * 8 + gc;
            float bx = bias[n], by = bias[n + 1];
#pragma unroll
            for (int half = 0; half < 2; half++) {
                int m = bm + wm * 32 + mi * 16 + gr + half * 8;
                float vx = acc[mi][ni][half * 2 + 0] + bx;
                float vy = acc[mi][ni][half * 2 + 1] + by;
                float2 o; o.x = vx; o.y = vy;
                if (MODE == 1) {
                    int b = m >> 10, t = m & (Tt - 1);
                    int h = n >> 6, e = n & (HS - 1);
                    *(float2*)(g_val + ((size_t)((b * NH + h) * Tt + t)) * HS + e) = o;
                } else {
                    *(float2*)(Cout + (size_t)m * N + n) = o;
                }
            }
        }
    }
}

// ---------------------------------------------------------------------------
// pos_feat[j,k] = sum_e rel[j,e] * W_pos[k,e]   (64x16)
// ---------------------------------------------------------------------------
__global__ void posfeat_kernel(const float* __restrict__ rel,
                               const float* __restrict__ Wpos)
{
    int i = threadIdx.x;
    int j = i >> 4, k = i & 15;
    float s = 0.f;
#pragma unroll
    for (int e = 0; e < BD; e++) s += rel[j * BD + e] * Wpos[k * BD + e];
    g_pos[j * BD + k] = s;
}

// ---------------------------------------------------------------------------
// qproj: g_Q[token][o] = sum_d W_fused[o][d] * g_disp[token][d]
// 2 threads per token (each 16 outputs).
// ---------------------------------------------------------------------------
__global__ __launch_bounds__(256) void qproj_kernel(const float* __restrict__ Wf)
{
    __shared__ float Wfs[32 * BD];
    int tid = threadIdx.x;
    for (int i = tid; i < 32 * BD; i += 256) Wfs[i] = Wf[i];
    __syncthreads();

    int gidx = blockIdx.x * 256 + tid;
    size_t token = gidx >> 1;
    int half = gidx & 1;           // outputs [half*16, half*16+16)
    float d[BD];
    const float4* dp = (const float4*)(g_disp + token * BD);
#pragma unroll
    for (int q = 0; q < 4; q++) {
        float4 v = dp[q];
        d[q * 4 + 0] = v.x; d[q * 4 + 1] = v.y;
        d[q * 4 + 2] = v.z; d[q * 4 + 3] = v.w;
    }
    float* qout = g_Q + token * 32 + half * 16;
    const float* wbase = Wfs + half * 16 * BD;
#pragma unroll
    for (int o4 = 0; o4 < 4; o4++) {
        float4 r;
        float s0 = 0.f, s1 = 0.f, s2 = 0.f, s3 = 0.f;
#pragma unroll
        for (int dd = 0; dd < BD; dd++) {
            s0 += wbase[(o4 * 4 + 0) * BD + dd] * d[dd];
            s1 += wbase[(o4 * 4 + 1) * BD + dd] * d[dd];
            s2 += wbase[(o4 * 4 + 2) * BD + dd] * d[dd];
            s3 += wbase[(o4 * 4 + 3) * BD + dd] * d[dd];
        }
        r.x = s0; r.y = s1; r.z = s2; r.w = s3;
        *(float4*)(qout + o4 * 4) = r;
    }
}

// ---------------------------------------------------------------------------
// Attention: one block (256 threads) per (b,h, 64-wide t-tile).
// Epilogue writes split-bf16 yh/yl directly (fused y-split).
// ---------------------------------------------------------------------------
struct AttnSmem {
    float QsT[32][132];
    float posB[16][64];
    float Wbs[16];
    float Wds[16];
    float Vs[127][64];
    float Wt[64][68];
};

__global__ __launch_bounds__(256) void attn_kernel(
    const float* __restrict__ b_fused,
    const float* __restrict__ W_bond, const float* __restrict__ b_bond,
    const float* __restrict__ W_dmg,  const float* __restrict__ b_dmg)
{
    extern __shared__ char smraw[];
    AttnSmem& sm = *reinterpret_cast<AttnSmem*>(smraw);

    const int bid = blockIdx.x;
    const int tile = bid & 15;
    const int bh = bid >> 4;
    const int t0 = tile * 64;
    const int tid = threadIdx.x;

    const float* __restrict__ Qbase = g_Q + (size_t)bh * Tt * 32;
    const float* __restrict__ Vbase = g_val + (size_t)bh * Tt * HS;

    for (int i = tid; i < 127 * 8; i += 256) {
        int r = i >> 3, kq = (i & 7) << 2;
        int tp = t0 - 63 + r;
        float4 v = make_float4(0.f, 0.f, 0.f, 0.f);
        if (tp >= 0) v = *(const float4*)(Qbase + (size_t)tp * 32 + kq);
        sm.QsT[kq + 0][r] = v.x; sm.QsT[kq + 1][r] = v.y;
        sm.QsT[kq + 2][r] = v.z; sm.QsT[kq + 3][r] = v.w;
    }
    for (int i = tid; i < 16 * 64; i += 256) {
        int k = i >> 6, j = i & 63;
        sm.posB[k][j] = g_pos[j * BD + k] + b_fused[k];
    }
    if (tid < 16) { sm.Wbs[tid] = W_bond[tid]; sm.Wds[tid] = W_dmg[tid]; }
    for (int i = tid; i < 127 * 16; i += 256) {
        int r = i >> 4, eq = (i & 15) << 2;
        int tp = t0 - 63 + r;
        float4 v = make_float4(0.f, 0.f, 0.f, 0.f);
        if (tp >= 0) v = *(const float4*)(Vbase + (size_t)tp * HS + eq);
        *(float4*)&sm.Vs[r][eq] = v;
    }
    __syncthreads();

    const int tq = tid & 63;
    const int jc = tid >> 6;
    const int c = tq + 63;

    float bond[16], dmg[16];
#pragma unroll
    for (int jj = 0; jj < 16; jj++) { bond[jj] = 0.f; dmg[jj] = 0.f; }

#pragma unroll
    for (int k = 0; k < 16; k++) {
        float qbc = sm.QsT[k][c];
        float qdc = sm.QsT[16 + k][c] - b_fused[16 + k];
        float wb = sm.Wbs[k];
        float wd = sm.Wds[k];
#pragma unroll
        for (int jj = 0; jj < 16; jj++) {
            int j = jc * 16 + jj;
            int r = tq + j;
            float db = sm.QsT[k][r] - qbc + sm.posB[k][j];
            float dd = sm.QsT[16 + k][r] - qdc;
            float argb = db * (0.7978845608f + 0.0356774081f * db * db);
            float argd = dd * (0.7978845608f + 0.0356774081f * dd * dd);
            float thb, thd;
            asm("tanh.approx.f32 %0, %1;" : "=f"(thb) : "f"(argb));
            asm("tanh.approx.f32 %0, %1;" : "=f"(thd) : "f"(argd));
            bond[jj] += 0.5f * db * (1.f + thb) * wb;
            dmg[jj]  += 0.5f * dd * (1.f + thd) * wd;
        }
    }
    {
        float bb = b_bond[0];
        float bdm = b_dmg[0];
#pragma unroll
        for (int jj = 0; jj < 16; jj++) {
            int j = jc * 16 + jj;
            float sig = 1.f / (1.f + __expf(-(dmg[jj] + bdm)));
            float logit = bond[jj] + bb - 10.f * sig;
            if (t0 + tq - 63 + j < 0) logit = -CUDART_INF_F;
            sm.Wt[tq][j] = logit;
        }
    }
    __syncthreads();

    if (tid < 64) {
        float mx = -CUDART_INF_F;
#pragma unroll
        for (int j = 0; j < 64; j++) mx = fmaxf(mx, sm.Wt[tid][j]);
        float s = 0.f;
#pragma unroll
        for (int j = 0; j < 64; j++) {
            float e = __expf(sm.Wt[tid][j] - mx);
            sm.Wt[tid][j] = e;
            s += e;
        }
        float inv = 1.f / s;
#pragma unroll
        for (int j = 0; j < 64; j++) sm.Wt[tid][j] *= inv;
    }
    __syncthreads();

    const int wrp = tid >> 5;
    const int l = tid & 31;
    const int b = bh >> 4;
    const int h = bh & (NH - 1);

    for (int q = 0; q < 8; q++) {
        int t = wrp * 8 + q;
        unsigned long long acc = 0ULL;
#pragma unroll
        for (int j = 0; j < 64; j += 4) {
            float4 wv = *(const float4*)&sm.Wt[t][j];
            fma2(acc, pack2(wv.x, wv.x),
                 *(const unsigned long long*)&sm.Vs[t + j + 0][2 * l]);
            fma2(acc, pack2(wv.y, wv.y),
                 *(const unsigned long long*)&sm.Vs[t + j + 1][2 * l]);
            fma2(acc, pack2(wv.z, wv.z),
                 *(const unsigned long long*)&sm.Vs[t + j + 2][2 * l]);
            fma2(acc, pack2(wv.w, wv.w),
                 *(const unsigned long long*)&sm.Vs[t + j + 3][2 * l]);
        }
        float ox, oy;
        unpack2(acc, ox, oy);
        // fused split into bf16 hi/lo
        __nv_bfloat16 h0 = __float2bfloat16(ox);
        __nv_bfloat16 h1 = __float2bfloat16(oy);
        __nv_bfloat16 l0 = __float2bfloat16(ox - __bfloat162float(h0));
        __nv_bfloat16 l1 = __float2bfloat16(oy - __bfloat162float(h1));
        size_t idx = ((size_t)(b * Tt + t0 + t)) * Cc + h * HS + 2 * l;
        __nv_bfloat162 hv; hv.x = h0; hv.y = h1;
        __nv_bfloat162 lv; lv.x = l0; lv.y = l1;
        *(__nv_bfloat162*)(g_yh + idx) = hv;
        *(__nv_bfloat162*)(g_yl + idx) = lv;
    }
}

// ---------------------------------------------------------------------------
// Launch
// ---------------------------------------------------------------------------
extern "C" void kernel_launch(void* const* d_in, const int* in_sizes, int n_in,
                              void* d_out, int out_size)
{
    const float* x       = (const float*)d_in[0];
    const float* W_disp  = (const float*)d_in[1];
    const float* b_disp  = (const float*)d_in[2];
    const float* W_val   = (const float*)d_in[3];
    const float* b_val   = (const float*)d_in[4];
    const float* rel     = (const float*)d_in[5];
    const float* W_fused = (const float*)d_in[6];
    const float* b_fused = (const float*)d_in[7];
    const float* W_pos   = (const float*)d_in[8];
    const float* W_bond  = (const float*)d_in[9];
    const float* b_bond  = (const float*)d_in[10];
    const float* W_dmg   = (const float*)d_in[11];
    const float* b_dmg   = (const float*)d_in[12];
    const float* W_cproj = (const float*)d_in[13];
    const float* b_cproj = (const float*)d_in[14];
    float* out = (float*)d_out;

    const int M = Bb * Tt;   // 2048
    const int K = Cc;        // 1024

    __nv_bfloat16 *xh, *xl, *wdh, *wdl, *wvh, *wvl, *wch, *wcl, *yh, *yl;
    void* p;
    cudaGetSymbolAddress(&p, g_xh);  xh  = (__nv_bfloat16*)p;
    cudaGetSymbolAddress(&p, g_xl);  xl  = (__nv_bfloat16*)p;
    cudaGetSymbolAddress(&p, g_wdh); wdh = (__nv_bfloat16*)p;
    cudaGetSymbolAddress(&p, g_wdl); wdl = (__nv_bfloat16*)p;
    cudaGetSymbolAddress(&p, g_wvh); wvh = (__nv_bfloat16*)p;
    cudaGetSymbolAddress(&p, g_wvl); wvl = (__nv_bfloat16*)p;
    cudaGetSymbolAddress(&p, g_wch); wch = (__nv_bfloat16*)p;
    cudaGetSymbolAddress(&p, g_wcl); wcl = (__nv_bfloat16*)p;
    cudaGetSymbolAddress(&p, g_yh);  yh  = (__nv_bfloat16*)p;
    cudaGetSymbolAddress(&p, g_yl);  yl  = (__nv_bfloat16*)p;

    // Splits of GEMM inputs
    split_kernel<<<(M * K / 2) / 256, 256>>>(x, xh, xl);
    split_kernel<<<(NH * BD * K / 2) / 256, 256>>>(W_disp, wdh, wdl);
    split_kernel<<<(K * K / 2) / 256, 256>>>(W_val, wvh, wvl);
    split_kernel<<<(K * K / 2) / 256, 256>>>(W_cproj, wch, wcl);

    const int SMEM_BIG = STAGE_ELEMS * 2 * 2;   // 81920 bytes
    cudaFuncSetAttribute(mma_gemm_big<1>, cudaFuncAttributeMaxDynamicSharedMemorySize, SMEM_BIG);
    cudaFuncSetAttribute(mma_gemm_big<2>, cudaFuncAttributeMaxDynamicSharedMemorySize, SMEM_BIG);

    dim3 gd(M / MT, (NH * BD) / NT);   // 16 x 4
    mma_gemm_disp<<<gd, 256>>>(xh, xl, wdh, wdl, b_disp, M, NH * BD, K);

    dim3 gv(M / MT, Cc / NT2);         // 16 x 8
    mma_gemm_big<1><<<gv, 256, SMEM_BIG>>>(xh, xl, wvh, wvl, b_val, nullptr, M, Cc, K);

    posfeat_kernel<<<1, DELTA * BD>>>(rel, W_pos);
    qproj_kernel<<<(2 * Bb * NH * Tt) / 256, 256>>>(W_fused);

    cudaFuncSetAttribute(attn_kernel, cudaFuncAttributeMaxDynamicSharedMemorySize,
                         (int)sizeof(AttnSmem));
    attn_kernel<<<Bb * NH * (Tt / DELTA), 256, sizeof(AttnSmem)>>>(
        b_fused, W_bond, b_bond, W_dmg, b_dmg);

    dim3 gc(M / MT, Cc / NT2);         // 16 x 8
    mma_gemm_big<2><<<gc, 256, SMEM_BIG>>>(yh, yl, wch, wcl, b_cproj, out, M, Cc, K);
}

// round 10
// speedup vs baseline: 2.5736x; 1.0396x over previous
#include <cuda_runtime.h>
#include <cuda_bf16.h>
#include <math_constants.h>
#include <cstddef>
#include <cstdint>

// Problem constants
#define Bb 2
#define Tt 1024
#define Cc 1024
#define NH 16
#define HS 64
#define BD 16
#define DELTA 64

// ---------------------------------------------------------------------------
// Scratch (device globals; no allocation allowed)
// ---------------------------------------------------------------------------
__device__ float g_disp[(size_t)Bb * NH * Tt * BD];   // (B,NH,T,BD)
__device__ float g_val [(size_t)Bb * NH * Tt * HS];   // (B,NH,T,HS)
__device__ float g_Q   [(size_t)Bb * NH * Tt * 32];   // (B,NH,T,32)
__device__ float g_pos [DELTA * BD];                  // (64,16)

// Split-bf16 operands
__device__ __nv_bfloat16 g_xh [(size_t)Bb * Tt * Cc];
__device__ __nv_bfloat16 g_xl [(size_t)Bb * Tt * Cc];
__device__ __nv_bfloat16 g_wdh[(size_t)NH * BD * Cc];
__device__ __nv_bfloat16 g_wdl[(size_t)NH * BD * Cc];
__device__ __nv_bfloat16 g_wvh[(size_t)Cc * Cc];
__device__ __nv_bfloat16 g_wvl[(size_t)Cc * Cc];
__device__ __nv_bfloat16 g_wch[(size_t)Cc * Cc];
__device__ __nv_bfloat16 g_wcl[(size_t)Cc * Cc];
__device__ __nv_bfloat16 g_yh [(size_t)Bb * Tt * Cc];
__device__ __nv_bfloat16 g_yl [(size_t)Bb * Tt * Cc];

// ---------------------------------------------------------------------------
// Packed f32x2 helpers
// ---------------------------------------------------------------------------
__device__ __forceinline__ unsigned long long pack2(float lo, float hi) {
    unsigned long long r;
    asm("mov.b64 %0, {%1, %2};" : "=l"(r) : "f"(lo), "f"(hi));
    return r;
}
__device__ __forceinline__ void unpack2(unsigned long long v, float& lo, float& hi) {
    asm("mov.b64 {%0, %1}, %2;" : "=f"(lo), "=f"(hi) : "l"(v));
}
__device__ __forceinline__ void fma2(unsigned long long& acc,
                                     unsigned long long a, unsigned long long b) {
    asm("fma.rn.f32x2 %0, %1, %2, %0;" : "+l"(acc) : "l"(a), "l"(b));
}

// ---------------------------------------------------------------------------
// mma.sync / ldmatrix / cp.async helpers (sm_80+ baseline PTX)
// ---------------------------------------------------------------------------
__device__ __forceinline__ uint32_t smem_u32(const void* p) {
    uint32_t a;
    asm("{ .reg .u64 t; cvta.to.shared.u64 t, %1; cvt.u32.u64 %0, t; }"
        : "=r"(a) : "l"(p));
    return a;
}
__device__ __forceinline__ void ldsm_x4(uint32_t& r0, uint32_t& r1,
                                        uint32_t& r2, uint32_t& r3, uint32_t addr) {
    asm volatile("ldmatrix.sync.aligned.m8n8.x4.shared.b16 {%0,%1,%2,%3}, [%4];"
                 : "=r"(r0), "=r"(r1), "=r"(r2), "=r"(r3) : "r"(addr));
}
__device__ __forceinline__ void mma_bf16(float* c, const uint32_t* a,
                                         uint32_t b0, uint32_t b1) {
    asm volatile(
        "mma.sync.aligned.m16n8k16.row.col.f32.bf16.bf16.f32 "
        "{%0,%1,%2,%3}, {%4,%5,%6,%7}, {%8,%9}, {%0,%1,%2,%3};"
        : "+f"(c[0]), "+f"(c[1]), "+f"(c[2]), "+f"(c[3])
        : "r"(a[0]), "r"(a[1]), "r"(a[2]), "r"(a[3]), "r"(b0), "r"(b1));
}
__device__ __forceinline__ void cp16(uint32_t saddr, const void* gptr) {
    asm volatile("cp.async.cg.shared.global [%0], [%1], 16;"
                 :: "r"(saddr), "l"(gptr));
}
#define CP_COMMIT() asm volatile("cp.async.commit_group;" ::: "memory")
#define CP_WAIT(n)  asm volatile("cp.async.wait_group %0;" :: "n"(n) : "memory")

// ---------------------------------------------------------------------------
// Split fp32 -> bf16 hi + lo, 4 elements per thread (float4 / uint2)
// ---------------------------------------------------------------------------
__global__ __launch_bounds__(256) void split_kernel(
    const float* __restrict__ src,
    __nv_bfloat16* __restrict__ hi, __nv_bfloat16* __restrict__ lo)
{
    int i = blockIdx.x * 256 + threadIdx.x;
    float4 v = ((const float4*)src)[i];
    __nv_bfloat16 h0 = __float2bfloat16(v.x);
    __nv_bfloat16 h1 = __float2bfloat16(v.y);
    __nv_bfloat16 h2 = __float2bfloat16(v.z);
    __nv_bfloat16 h3 = __float2bfloat16(v.w);
    __nv_bfloat16 l0 = __float2bfloat16(v.x - __bfloat162float(h0));
    __nv_bfloat16 l1 = __float2bfloat16(v.y - __bfloat162float(h1));
    __nv_bfloat16 l2 = __float2bfloat16(v.z - __bfloat162float(h2));
    __nv_bfloat16 l3 = __float2bfloat16(v.w - __bfloat162float(h3));
    __nv_bfloat162 hv0; hv0.x = h0; hv0.y = h1;
    __nv_bfloat162 hv1; hv1.x = h2; hv1.y = h3;
    __nv_bfloat162 lv0; lv0.x = l0; lv0.y = l1;
    __nv_bfloat162 lv1; lv1.x = l2; lv1.y = l3;
    uint2 hp, lp;
    hp.x = *(uint32_t*)&hv0; hp.y = *(uint32_t*)&hv1;
    lp.x = *(uint32_t*)&lv0; lp.y = *(uint32_t*)&lv1;
    ((uint2*)hi)[i] = hp;
    ((uint2*)lo)[i] = lp;
}

// ---------------------------------------------------------------------------
// disp GEMM (small N): split-bf16 mma.sync, BM=128 x BN=64 x BK=32,
// 8 warps (4m x 2n), warp tile 32x32. Single-buffered (proven correct R8).
// ---------------------------------------------------------------------------
#define MT 128
#define NT 64
#define KB 32
#define RS 40   // smem row stride in bf16 elements

__global__ __launch_bounds__(256)
void mma_gemm_disp(const __nv_bfloat16* __restrict__ Ah, const __nv_bfloat16* __restrict__ Al,
                   const __nv_bfloat16* __restrict__ Bh, const __nv_bfloat16* __restrict__ Bl,
                   const float* __restrict__ bias, int M, int N, int K)
{
    __shared__ __nv_bfloat16 sAh[MT * RS];
    __shared__ __nv_bfloat16 sAl[MT * RS];
    __shared__ __nv_bfloat16 sBh[NT * RS];
    __shared__ __nv_bfloat16 sBl[NT * RS];

    const int tid = threadIdx.x;
    const int wid = tid >> 5, lane = tid & 31;
    const int wm = wid & 3;
    const int wn = wid >> 2;
    const int bm = blockIdx.x * MT;
    const int bn = blockIdx.y * NT;

    float acc[2][4][4];
#pragma unroll
    for (int mi = 0; mi < 2; mi++)
#pragma unroll
        for (int ni = 0; ni < 4; ni++)
#pragma unroll
            for (int q = 0; q < 4; q++) acc[mi][ni][q] = 0.f;

    const uint32_t aAh = smem_u32(sAh), aAl = smem_u32(sAl);
    const uint32_t aBh = smem_u32(sBh), aBl = smem_u32(sBl);
    const int a_row_in = (lane & 15);
    const int a_col8 = (lane >> 4) * 8;
    const int b_row_in = ((lane >> 4) << 3) + (lane & 7);
    const int b_col8 = ((lane >> 3) & 1) * 8;

    for (int k0 = 0; k0 < K; k0 += KB) {
#pragma unroll
        for (int t = 0; t < 2; t++) {
            int i = tid + t * 256;
            int row = i >> 2, q = i & 3;
            size_t go = (size_t)(bm + row) * K + k0 + q * 8;
            int so = row * RS + q * 8;
            *(uint4*)(sAh + so) = *(const uint4*)(Ah + go);
            *(uint4*)(sAl + so) = *(const uint4*)(Al + go);
        }
        {
            int row = tid >> 2, q = tid & 3;
            size_t go = (size_t)(bn + row) * K + k0 + q * 8;
            int so = row * RS + q * 8;
            *(uint4*)(sBh + so) = *(const uint4*)(Bh + go);
            *(uint4*)(sBl + so) = *(const uint4*)(Bl + go);
        }
        __syncthreads();

#pragma unroll
        for (int kst = 0; kst < 2; kst++) {
            const int kc = kst * 16;
            uint32_t ah[2][4], al[2][4];
#pragma unroll
            for (int mi = 0; mi < 2; mi++) {
                int off = ((wm * 32 + mi * 16 + a_row_in) * RS + kc + a_col8) * 2;
                ldsm_x4(ah[mi][0], ah[mi][1], ah[mi][2], ah[mi][3], aAh + off);
                ldsm_x4(al[mi][0], al[mi][1], al[mi][2], al[mi][3], aAl + off);
            }
            uint32_t bh[4][2], bl[4][2];
#pragma unroll
            for (int ng = 0; ng < 2; ng++) {
                int off = ((wn * 32 + ng * 16 + b_row_in) * RS + kc + b_col8) * 2;
                uint32_t r0, r1, r2, r3;
                ldsm_x4(r0, r1, r2, r3, aBh + off);
                bh[ng * 2 + 0][0] = r0; bh[ng * 2 + 0][1] = r1;
                bh[ng * 2 + 1][0] = r2; bh[ng * 2 + 1][1] = r3;
                ldsm_x4(r0, r1, r2, r3, aBl + off);
                bl[ng * 2 + 0][0] = r0; bl[ng * 2 + 0][1] = r1;
                bl[ng * 2 + 1][0] = r2; bl[ng * 2 + 1][1] = r3;
            }
#pragma unroll
            for (int mi = 0; mi < 2; mi++)
#pragma unroll
                for (int ni = 0; ni < 4; ni++) {
                    mma_bf16(acc[mi][ni], ah[mi], bh[ni][0], bh[ni][1]);
                    mma_bf16(acc[mi][ni], ah[mi], bl[ni][0], bl[ni][1]);
                    mma_bf16(acc[mi][ni], al[mi], bh[ni][0], bh[ni][1]);
                }
        }
        __syncthreads();
    }

    const int gr = lane >> 2;
    const int gc = (lane & 3) * 2;
#pragma unroll
    for (int mi = 0; mi < 2; mi++) {
#pragma unroll
        for (int ni = 0; ni < 4; ni++) {
            int n = bn + wn * 32 + ni * 8 + gc;
            float bx = bias[n], by = bias[n + 1];
#pragma unroll
            for (int half = 0; half < 2; half++) {
                int m = bm + wm * 32 + mi * 16 + gr + half * 8;
                float vx = acc[mi][ni][half * 2 + 0] + bx;
                float vy = acc[mi][ni][half * 2 + 1] + by;
                int b = m >> 10, t = m & (Tt - 1);
                int h = n >> 4, d = n & (BD - 1);
                float2 o; o.x = vx; o.y = vy;
                *(float2*)(g_disp + ((size_t)((b * NH + h) * Tt + t)) * BD + d) = o;
            }
        }
    }
}

// ---------------------------------------------------------------------------
// Big GEMM: BM=128 x BN=128 x BK=32, cp.async double-buffered.
// 4 warps (2m x 2n), warp tile 64x64 (4 x 8 m16n8 fragments).
// MODE 1: scatter to g_val; MODE 2: plain -> Cout.
// Dynamic smem: 2 stages x 4 tiles x 128 x RS bf16 = 81920 B.
// ---------------------------------------------------------------------------
#define NT2 128
#define STAGE_ELEMS (4 * 128 * RS)              // bf16 per stage = 20480

template<int MODE>
__global__ __launch_bounds__(128, 2)
void mma_gemm_big(const __nv_bfloat16* __restrict__ Ah, const __nv_bfloat16* __restrict__ Al,
                  const __nv_bfloat16* __restrict__ Bh, const __nv_bfloat16* __restrict__ Bl,
                  const float* __restrict__ bias, float* __restrict__ Cout,
                  int M, int N, int K)
{
    extern __shared__ __nv_bfloat16 smem[];

    const int tid = threadIdx.x;
    const int wid = tid >> 5, lane = tid & 31;
    const int wm = wid & 1;          // 64-row group
    const int wn = wid >> 1;         // 64-col group
    const int bm = blockIdx.x * MT;
    const int bn = blockIdx.y * NT2;

    float acc[4][8][4];
#pragma unroll
    for (int mi = 0; mi < 4; mi++)
#pragma unroll
        for (int ni = 0; ni < 8; ni++)
#pragma unroll
            for (int q = 0; q < 4; q++) acc[mi][ni][q] = 0.f;

    const uint32_t sbase = smem_u32(smem);
    const int a_row_in = (lane & 15);
    const int a_col8 = (lane >> 4) * 8;
    const int b_row_in = ((lane >> 4) << 3) + (lane & 7);
    const int b_col8 = ((lane >> 3) & 1) * 8;

    // cp.async assignment: 128 threads, per tile 512 x 16B -> 4 per thread
    const int l_row = tid >> 2;            // 0..31
    const int l_q = tid & 3;               // 16B quarter

    const int nch = K / KB;

    auto load_stage = [&](int stage, int k0) {
        uint32_t sb = sbase + stage * STAGE_ELEMS * 2;
#pragma unroll
        for (int t = 0; t < 4; t++) {
            int row = l_row + t * 32;      // 0..127
            int so = (row * RS + l_q * 8) * 2;
            size_t go = (size_t)(bm + row) * K + k0 + l_q * 8;
            cp16(sb + so, Ah + go);
            cp16(sb + (128 * RS) * 2 + so, Al + go);
        }
#pragma unroll
        for (int t = 0; t < 4; t++) {
            int row = l_row + t * 32;
            int so = (row * RS + l_q * 8) * 2;
            size_t go = (size_t)(bn + row) * K + k0 + l_q * 8;
            cp16(sb + (2 * 128 * RS) * 2 + so, Bh + go);
            cp16(sb + (3 * 128 * RS) * 2 + so, Bl + go);
        }
    };

    load_stage(0, 0);
    CP_COMMIT();

    for (int ch = 0; ch < nch; ch++) {
        const int cur = ch & 1;
        if (ch + 1 < nch) {
            load_stage(cur ^ 1, (ch + 1) * KB);
            CP_COMMIT();
            CP_WAIT(1);
        } else {
            CP_WAIT(0);
        }
        __syncthreads();

        const uint32_t sb = sbase + cur * STAGE_ELEMS * 2;
        const uint32_t aAh = sb;
        const uint32_t aAl = sb + (128 * RS) * 2;
        const uint32_t aBh = sb + (2 * 128 * RS) * 2;
        const uint32_t aBl = sb + (3 * 128 * RS) * 2;

#pragma unroll
        for (int kst = 0; kst < 2; kst++) {
            const int kc = kst * 16;
            uint32_t ah[4][4], al[4][4];
#pragma unroll
            for (int mi = 0; mi < 4; mi++) {
                int off = ((wm * 64 + mi * 16 + a_row_in) * RS + kc + a_col8) * 2;
                ldsm_x4(ah[mi][0], ah[mi][1], ah[mi][2], ah[mi][3], aAh + off);
                ldsm_x4(al[mi][0], al[mi][1], al[mi][2], al[mi][3], aAl + off);
            }
#pragma unroll
            for (int ng = 0; ng < 4; ng++) {
                int off = ((wn * 64 + ng * 16 + b_row_in) * RS + kc + b_col8) * 2;
                uint32_t h0, h1, h2, h3, lo0, lo1, lo2, lo3;
                ldsm_x4(h0, h1, h2, h3, aBh + off);
                ldsm_x4(lo0, lo1, lo2, lo3, aBl + off);
#pragma unroll
                for (int mi = 0; mi < 4; mi++) {
                    mma_bf16(acc[mi][ng * 2 + 0], ah[mi], h0, h1);
                    mma_bf16(acc[mi][ng * 2 + 0], ah[mi], lo0, lo1);
                    mma_bf16(acc[mi][ng * 2 + 0], al[mi], h0, h1);
                    mma_bf16(acc[mi][ng * 2 + 1], ah[mi], h2, h3);
                    mma_bf16(acc[mi][ng * 2 + 1], ah[mi], lo2, lo3);
                    mma_bf16(acc[mi][ng * 2 + 1], al[mi], h2, h3);
                }
            }
        }
        __syncthreads();
    }

    // ---- epilogue ----
    const int gr = lane >> 2;
    const int gc = (lane & 3) * 2;
#pragma unroll
    for (int mi = 0; mi < 4; mi++) {
#pragma unroll
        for (int ni = 0; ni < 8; ni++) {
            int n = bn + wn * 64 + ni * 8 + gc;
            float bx = bias[n], by = bias[n + 1];
#pragma unroll
            for (int half = 0; half < 2; half++) {
                int m = bm + wm * 64 + mi * 16 + gr + half * 8;
                float vx = acc[mi][ni][half * 2 + 0] + bx;
                float vy = acc[mi][ni][half * 2 + 1] + by;
                float2 o; o.x = vx; o.y = vy;
                if (MODE == 1) {
                    int b = m >> 10, t = m & (Tt - 1);
                    int h = n >> 6, e = n & (HS - 1);
                    *(float2*)(g_val + ((size_t)((b * NH + h) * Tt + t)) * HS + e) = o;
                } else {
                    *(float2*)(Cout + (size_t)m * N + n) = o;
                }
            }
        }
    }
}

// ---------------------------------------------------------------------------
// pos_feat[j,k] = sum_e rel[j,e] * W_pos[k,e]   (64x16)
// ---------------------------------------------------------------------------
__global__ void posfeat_kernel(const float* __restrict__ rel,
                               const float* __restrict__ Wpos)
{
    int i = threadIdx.x;
    int j = i >> 4, k = i & 15;
    float s = 0.f;
#pragma unroll
    for (int e = 0; e < BD; e++) s += rel[j * BD + e] * Wpos[k * BD + e];
    g_pos[j * BD + k] = s;
}

// ---------------------------------------------------------------------------
// qproj: g_Q[token][o] = sum_d W_fused[o][d] * g_disp[token][d]
// 2 threads per token (each 16 outputs).
// ---------------------------------------------------------------------------
__global__ __launch_bounds__(256) void qproj_kernel(const float* __restrict__ Wf)
{
    __shared__ float Wfs[32 * BD];
    int tid = threadIdx.x;
    for (int i = tid; i < 32 * BD; i += 256) Wfs[i] = Wf[i];
    __syncthreads();

    int gidx = blockIdx.x * 256 + tid;
    size_t token = gidx >> 1;
    int half = gidx & 1;
    float d[BD];
    const float4* dp = (const float4*)(g_disp + token * BD);
#pragma unroll
    for (int q = 0; q < 4; q++) {
        float4 v = dp[q];
        d[q * 4 + 0] = v.x; d[q * 4 + 1] = v.y;
        d[q * 4 + 2] = v.z; d[q * 4 + 3] = v.w;
    }
    float* qout = g_Q + token * 32 + half * 16;
    const float* wbase = Wfs + half * 16 * BD;
#pragma unroll
    for (int o4 = 0; o4 < 4; o4++) {
        float4 r;
        float s0 = 0.f, s1 = 0.f, s2 = 0.f, s3 = 0.f;
#pragma unroll
        for (int dd = 0; dd < BD; dd++) {
            s0 += wbase[(o4 * 4 + 0) * BD + dd] * d[dd];
            s1 += wbase[(o4 * 4 + 1) * BD + dd] * d[dd];
            s2 += wbase[(o4 * 4 + 2) * BD + dd] * d[dd];
            s3 += wbase[(o4 * 4 + 3) * BD + dd] * d[dd];
        }
        r.x = s0; r.y = s1; r.z = s2; r.w = s3;
        *(float4*)(qout + o4 * 4) = r;
    }
}

// ---------------------------------------------------------------------------
// Attention: one block (256 threads) per (b,h, 64-wide t-tile).
// Epilogue writes split-bf16 yh/yl directly.
// ---------------------------------------------------------------------------
struct AttnSmem {
    float QsT[32][132];
    float posB[16][64];
    float Wbs[16];
    float Wds[16];
    float Vs[127][64];
    float Wt[64][68];
};

__global__ __launch_bounds__(256) void attn_kernel(
    const float* __restrict__ b_fused,
    const float* __restrict__ W_bond, const float* __restrict__ b_bond,
    const float* __restrict__ W_dmg,  const float* __restrict__ b_dmg)
{
    extern __shared__ char smraw[];
    AttnSmem& sm = *reinterpret_cast<AttnSmem*>(smraw);

    const int bid = blockIdx.x;
    const int tile = bid & 15;
    const int bh = bid >> 4;
    const int t0 = tile * 64;
    const int tid = threadIdx.x;

    const float* __restrict__ Qbase = g_Q + (size_t)bh * Tt * 32;
    const float* __restrict__ Vbase = g_val + (size_t)bh * Tt * HS;

    for (int i = tid; i < 127 * 8; i += 256) {
        int r = i >> 3, kq = (i & 7) << 2;
        int tp = t0 - 63 + r;
        float4 v = make_float4(0.f, 0.f, 0.f, 0.f);
        if (tp >= 0) v = *(const float4*)(Qbase + (size_t)tp * 32 + kq);
        sm.QsT[kq + 0][r] = v.x; sm.QsT[kq + 1][r] = v.y;
        sm.QsT[kq + 2][r] = v.z; sm.QsT[kq + 3][r] = v.w;
    }
    for (int i = tid; i < 16 * 64; i += 256) {
        int k = i >> 6, j = i & 63;
        sm.posB[k][j] = g_pos[j * BD + k] + b_fused[k];
    }
    if (tid < 16) { sm.Wbs[tid] = W_bond[tid]; sm.Wds[tid] = W_dmg[tid]; }
    for (int i = tid; i < 127 * 16; i += 256) {
        int r = i >> 4, eq = (i & 15) << 2;
        int tp = t0 - 63 + r;
        float4 v = make_float4(0.f, 0.f, 0.f, 0.f);
        if (tp >= 0) v = *(const float4*)(Vbase + (size_t)tp * HS + eq);
        *(float4*)&sm.Vs[r][eq] = v;
    }
    __syncthreads();

    const int tq = tid & 63;
    const int jc = tid >> 6;
    const int c = tq + 63;

    float bond[16], dmg[16];
#pragma unroll
    for (int jj = 0; jj < 16; jj++) { bond[jj] = 0.f; dmg[jj] = 0.f; }

#pragma unroll
    for (int k = 0; k < 16; k++) {
        float qbc = sm.QsT[k][c];
        float qdc = sm.QsT[16 + k][c] - b_fused[16 + k];
        float wb = sm.Wbs[k];
        float wd = sm.Wds[k];
#pragma unroll
        for (int jj = 0; jj < 16; jj++) {
            int j = jc * 16 + jj;
            int r = tq + j;
            float db = sm.QsT[k][r] - qbc + sm.posB[k][j];
            float dd = sm.QsT[16 + k][r] - qdc;
            float argb = db * (0.7978845608f + 0.0356774081f * db * db);
            float argd = dd * (0.7978845608f + 0.0356774081f * dd * dd);
            float thb, thd;
            asm("tanh.approx.f32 %0, %1;" : "=f"(thb) : "f"(argb));
            asm("tanh.approx.f32 %0, %1;" : "=f"(thd) : "f"(argd));
            bond[jj] += 0.5f * db * (1.f + thb) * wb;
            dmg[jj]  += 0.5f * dd * (1.f + thd) * wd;
        }
    }
    {
        float bb = b_bond[0];
        float bdm = b_dmg[0];
#pragma unroll
        for (int jj = 0; jj < 16; jj++) {
            int j = jc * 16 + jj;
            float sig = 1.f / (1.f + __expf(-(dmg[jj] + bdm)));
            float logit = bond[jj] + bb - 10.f * sig;
            if (t0 + tq - 63 + j < 0) logit = -CUDART_INF_F;
            sm.Wt[tq][j] = logit;
        }
    }
    __syncthreads();

    if (tid < 64) {
        float mx = -CUDART_INF_F;
#pragma unroll
        for (int j = 0; j < 64; j++) mx = fmaxf(mx, sm.Wt[tid][j]);
        float s = 0.f;
#pragma unroll
        for (int j = 0; j < 64; j++) {
            float e = __expf(sm.Wt[tid][j] - mx);
            sm.Wt[tid][j] = e;
            s += e;
        }
        float inv = 1.f / s;
#pragma unroll
        for (int j = 0; j < 64; j++) sm.Wt[tid][j] *= inv;
    }
    __syncthreads();

    const int wrp = tid >> 5;
    const int l = tid & 31;
    const int b = bh >> 4;
    const int h = bh & (NH - 1);

    for (int q = 0; q < 8; q++) {
        int t = wrp * 8 + q;
        unsigned long long acc = 0ULL;
#pragma unroll
        for (int j = 0; j < 64; j += 4) {
            float4 wv = *(const float4*)&sm.Wt[t][j];
            fma2(acc, pack2(wv.x, wv.x),
                 *(const unsigned long long*)&sm.Vs[t + j + 0][2 * l]);
            fma2(acc, pack2(wv.y, wv.y),
                 *(const unsigned long long*)&sm.Vs[t + j + 1][2 * l]);
            fma2(acc, pack2(wv.z, wv.z),
                 *(const unsigned long long*)&sm.Vs[t + j + 2][2 * l]);
            fma2(acc, pack2(wv.w, wv.w),
                 *(const unsigned long long*)&sm.Vs[t + j + 3][2 * l]);
        }
        float ox, oy;
        unpack2(acc, ox, oy);
        __nv_bfloat16 h0 = __float2bfloat16(ox);
        __nv_bfloat16 h1 = __float2bfloat16(oy);
        __nv_bfloat16 l0 = __float2bfloat16(ox - __bfloat162float(h0));
        __nv_bfloat16 l1 = __float2bfloat16(oy - __bfloat162float(h1));
        size_t idx = ((size_t)(b * Tt + t0 + t)) * Cc + h * HS + 2 * l;
        __nv_bfloat162 hv; hv.x = h0; hv.y = h1;
        __nv_bfloat162 lv; lv.x = l0; lv.y = l1;
        *(__nv_bfloat162*)(g_yh + idx) = hv;
        *(__nv_bfloat162*)(g_yl + idx) = lv;
    }
}

// ---------------------------------------------------------------------------
// Launch
// ---------------------------------------------------------------------------
extern "C" void kernel_launch(void* const* d_in, const int* in_sizes, int n_in,
                              void* d_out, int out_size)
{
    const float* x       = (const float*)d_in[0];
    const float* W_disp  = (const float*)d_in[1];
    const float* b_disp  = (const float*)d_in[2];
    const float* W_val   = (const float*)d_in[3];
    const float* b_val   = (const float*)d_in[4];
    const float* rel     = (const float*)d_in[5];
    const float* W_fused = (const float*)d_in[6];
    const float* b_fused = (const float*)d_in[7];
    const float* W_pos   = (const float*)d_in[8];
    const float* W_bond  = (const float*)d_in[9];
    const float* b_bond  = (const float*)d_in[10];
    const float* W_dmg   = (const float*)d_in[11];
    const float* b_dmg   = (const float*)d_in[12];
    const float* W_cproj = (const float*)d_in[13];
    const float* b_cproj = (const float*)d_in[14];
    float* out = (float*)d_out;

    const int M = Bb * Tt;   // 2048
    const int K = Cc;        // 1024

    __nv_bfloat16 *xh, *xl, *wdh, *wdl, *wvh, *wvl, *wch, *wcl, *yh, *yl;
    void* p;
    cudaGetSymbolAddress(&p, g_xh);  xh  = (__nv_bfloat16*)p;
    cudaGetSymbolAddress(&p, g_xl);  xl  = (__nv_bfloat16*)p;
    cudaGetSymbolAddress(&p, g_wdh); wdh = (__nv_bfloat16*)p;
    cudaGetSymbolAddress(&p, g_wdl); wdl = (__nv_bfloat16*)p;
    cudaGetSymbolAddress(&p, g_wvh); wvh = (__nv_bfloat16*)p;
    cudaGetSymbolAddress(&p, g_wvl); wvl = (__nv_bfloat16*)p;
    cudaGetSymbolAddress(&p, g_wch); wch = (__nv_bfloat16*)p;
    cudaGetSymbolAddress(&p, g_wcl); wcl = (__nv_bfloat16*)p;
    cudaGetSymbolAddress(&p, g_yh);  yh  = (__nv_bfloat16*)p;
    cudaGetSymbolAddress(&p, g_yl);  yl  = (__nv_bfloat16*)p;

    // Splits of GEMM inputs (4 elems/thread)
    split_kernel<<<(M * K / 4) / 256, 256>>>(x, xh, xl);
    split_kernel<<<(NH * BD * K / 4) / 256, 256>>>(W_disp, wdh, wdl);
    split_kernel<<<(K * K / 4) / 256, 256>>>(W_val, wvh, wvl);
    split_kernel<<<(K * K / 4) / 256, 256>>>(W_cproj, wch, wcl);

    const int SMEM_BIG = STAGE_ELEMS * 2 * 2;   // 81920 bytes
    cudaFuncSetAttribute(mma_gemm_big<1>, cudaFuncAttributeMaxDynamicSharedMemorySize, SMEM_BIG);
    cudaFuncSetAttribute(mma_gemm_big<2>, cudaFuncAttributeMaxDynamicSharedMemorySize, SMEM_BIG);

    dim3 gd(M / MT, (NH * BD) / NT);   // 16 x 4
    mma_gemm_disp<<<gd, 256>>>(xh, xl, wdh, wdl, b_disp, M, NH * BD, K);

    dim3 gv(M / MT, Cc / NT2);         // 16 x 8
    mma_gemm_big<1><<<gv, 128, SMEM_BIG>>>(xh, xl, wvh, wvl, b_val, nullptr, M, Cc, K);

    posfeat_kernel<<<1, DELTA * BD>>>(rel, W_pos);
    qproj_kernel<<<(2 * Bb * NH * Tt) / 256, 256>>>(W_fused);

    cudaFuncSetAttribute(attn_kernel, cudaFuncAttributeMaxDynamicSharedMemorySize,
                         (int)sizeof(AttnSmem));
    attn_kernel<<<Bb * NH * (Tt / DELTA), 256, sizeof(AttnSmem)>>>(
        b_fused, W_bond, b_bond, W_dmg, b_dmg);

    dim3 gc(M / MT, Cc / NT2);         // 16 x 8
    mma_gemm_big<2><<<gc, 128, SMEM_BIG>>>(yh, yl, wch, wcl, b_cproj, out, M, Cc, K);
}

// round 11
// speedup vs baseline: 2.6185x; 1.0174x over previous
#include <cuda_runtime.h>
#include <cuda_bf16.h>
#include <math_constants.h>
#include <cstddef>
#include <cstdint>

// Problem constants
#define Bb 2
#define Tt 1024
#define Cc 1024
#define NH 16
#define HS 64
#define BD 16
#define DELTA 64

// ---------------------------------------------------------------------------
// Scratch (device globals; no allocation allowed)
// ---------------------------------------------------------------------------
__device__ float g_disp[(size_t)Bb * NH * Tt * BD];   // (B,NH,T,BD)
__device__ float g_val [(size_t)Bb * NH * Tt * HS];   // (B,NH,T,HS)
__device__ float g_Q   [(size_t)Bb * NH * Tt * 32];   // (B,NH,T,32)
__device__ float g_pos [DELTA * BD];                  // (64,16)

// Split-bf16 operands
__device__ __nv_bfloat16 g_xh [(size_t)Bb * Tt * Cc];
__device__ __nv_bfloat16 g_xl [(size_t)Bb * Tt * Cc];
__device__ __nv_bfloat16 g_wdh[(size_t)NH * BD * Cc];
__device__ __nv_bfloat16 g_wdl[(size_t)NH * BD * Cc];
__device__ __nv_bfloat16 g_wvh[(size_t)Cc * Cc];
__device__ __nv_bfloat16 g_wvl[(size_t)Cc * Cc];
__device__ __nv_bfloat16 g_wch[(size_t)Cc * Cc];
__device__ __nv_bfloat16 g_wcl[(size_t)Cc * Cc];
__device__ __nv_bfloat16 g_yh [(size_t)Bb * Tt * Cc];
__device__ __nv_bfloat16 g_yl [(size_t)Bb * Tt * Cc];

// ---------------------------------------------------------------------------
// Packed f32x2 helpers
// ---------------------------------------------------------------------------
__device__ __forceinline__ unsigned long long pack2(float lo, float hi) {
    unsigned long long r;
    asm("mov.b64 %0, {%1, %2};" : "=l"(r) : "f"(lo), "f"(hi));
    return r;
}
__device__ __forceinline__ void unpack2(unsigned long long v, float& lo, float& hi) {
    asm("mov.b64 {%0, %1}, %2;" : "=f"(lo), "=f"(hi) : "l"(v));
}
__device__ __forceinline__ void fma2(unsigned long long& acc,
                                     unsigned long long a, unsigned long long b) {
    asm("fma.rn.f32x2 %0, %1, %2, %0;" : "+l"(acc) : "l"(a), "l"(b));
}

// ---------------------------------------------------------------------------
// mma.sync / ldmatrix / cp.async helpers (sm_80+ baseline PTX)
// ---------------------------------------------------------------------------
__device__ __forceinline__ uint32_t smem_u32(const void* p) {
    uint32_t a;
    asm("{ .reg .u64 t; cvta.to.shared.u64 t, %1; cvt.u32.u64 %0, t; }"
        : "=r"(a) : "l"(p));
    return a;
}
__device__ __forceinline__ void ldsm_x4(uint32_t& r0, uint32_t& r1,
                                        uint32_t& r2, uint32_t& r3, uint32_t addr) {
    asm volatile("ldmatrix.sync.aligned.m8n8.x4.shared.b16 {%0,%1,%2,%3}, [%4];"
                 : "=r"(r0), "=r"(r1), "=r"(r2), "=r"(r3) : "r"(addr));
}
__device__ __forceinline__ void mma_bf16(float* c, const uint32_t* a,
                                         uint32_t b0, uint32_t b1) {
    asm volatile(
        "mma.sync.aligned.m16n8k16.row.col.f32.bf16.bf16.f32 "
        "{%0,%1,%2,%3}, {%4,%5,%6,%7}, {%8,%9}, {%0,%1,%2,%3};"
        : "+f"(c[0]), "+f"(c[1]), "+f"(c[2]), "+f"(c[3])
        : "r"(a[0]), "r"(a[1]), "r"(a[2]), "r"(a[3]), "r"(b0), "r"(b1));
}
__device__ __forceinline__ void cp16(uint32_t saddr, const void* gptr) {
    asm volatile("cp.async.cg.shared.global [%0], [%1], 16;"
                 :: "r"(saddr), "l"(gptr));
}
#define CP_COMMIT() asm volatile("cp.async.commit_group;" ::: "memory")
#define CP_WAIT(n)  asm volatile("cp.async.wait_group %0;" :: "n"(n) : "memory")

// ---------------------------------------------------------------------------
// Fused split: one launch covers x, W_val, W_cproj, W_disp.
// 4 elems/thread; block segments: [0,2048) x, [2048,3072) Wv,
// [3072,4096) Wc, [4096,4352) Wd.
// ---------------------------------------------------------------------------
__global__ __launch_bounds__(256) void split_fused(
    const float* __restrict__ x, const float* __restrict__ Wv,
    const float* __restrict__ Wc, const float* __restrict__ Wd)
{
    const int b = blockIdx.x;
    const int tid = threadIdx.x;
    const float* src;
    __nv_bfloat16 *hi, *lo;
    int i;
    if (b < 2048)      { src = x;  hi = g_xh;  lo = g_xl;  i = b * 256 + tid; }
    else if (b < 3072) { src = Wv; hi = g_wvh; lo = g_wvl; i = (b - 2048) * 256 + tid; }
    else if (b < 4096) { src = Wc; hi = g_wch; lo = g_wcl; i = (b - 3072) * 256 + tid; }
    else               { src = Wd; hi = g_wdh; lo = g_wdl; i = (b - 4096) * 256 + tid; }

    float4 v = ((const float4*)src)[i];
    __nv_bfloat16 h0 = __float2bfloat16(v.x);
    __nv_bfloat16 h1 = __float2bfloat16(v.y);
    __nv_bfloat16 h2 = __float2bfloat16(v.z);
    __nv_bfloat16 h3 = __float2bfloat16(v.w);
    __nv_bfloat16 l0 = __float2bfloat16(v.x - __bfloat162float(h0));
    __nv_bfloat16 l1 = __float2bfloat16(v.y - __bfloat162float(h1));
    __nv_bfloat16 l2 = __float2bfloat16(v.z - __bfloat162float(h2));
    __nv_bfloat16 l3 = __float2bfloat16(v.w - __bfloat162float(h3));
    __nv_bfloat162 hv0; hv0.x = h0; hv0.y = h1;
    __nv_bfloat162 hv1; hv1.x = h2; hv1.y = h3;
    __nv_bfloat162 lv0; lv0.x = l0; lv0.y = l1;
    __nv_bfloat162 lv1; lv1.x = l2; lv1.y = l3;
    uint2 hp, lp;
    hp.x = *(uint32_t*)&hv0; hp.y = *(uint32_t*)&hv1;
    lp.x = *(uint32_t*)&lv0; lp.y = *(uint32_t*)&lv1;
    ((uint2*)hi)[i] = hp;
    ((uint2*)lo)[i] = lp;
}

// ---------------------------------------------------------------------------
// Big GEMM: BM=128 x BN=128 x BK=32, cp.async double-buffered.
// 4 warps (2m x 2n), warp tile 64x64 (4 x 8 m16n8 fragments).
// MODE 1: fused val+disp — grid.y = 10; by<8 -> B=(Bh,Bl), bias, scatter g_val;
//         by>=8 -> B=(B2h,B2l) rows (by-8)*128, bias2, scatter g_disp.
// MODE 2: plain -> Cout (grid.y = 8).
// Dynamic smem: 2 stages x 4 tiles x 128 x RS bf16 = 81920 B.
// ---------------------------------------------------------------------------
#define MT 128
#define NT2 128
#define KB 32
#define RS 40
#define STAGE_ELEMS (4 * 128 * RS)              // bf16 per stage = 20480

template<int MODE>
__global__ __launch_bounds__(128, 2)
void mma_gemm_big(const __nv_bfloat16* __restrict__ Ah, const __nv_bfloat16* __restrict__ Al,
                  const __nv_bfloat16* __restrict__ Bh, const __nv_bfloat16* __restrict__ Bl,
                  const __nv_bfloat16* __restrict__ B2h, const __nv_bfloat16* __restrict__ B2l,
                  const float* __restrict__ bias, const float* __restrict__ bias2,
                  float* __restrict__ Cout, int M, int N, int K)
{
    extern __shared__ __nv_bfloat16 smem[];

    const int tid = threadIdx.x;
    const int wid = tid >> 5, lane = tid & 31;
    const int wm = wid & 1;          // 64-row group
    const int wn = wid >> 1;         // 64-col group
    const int bm = blockIdx.x * MT;
    const int by = blockIdx.y;

    // Select B operand / bias / n-base for this tile
    const __nv_bfloat16* Bph;
    const __nv_bfloat16* Bpl;
    const float* bp;
    int bnr;                          // row base into chosen B
    bool is_disp = false;
    if (MODE == 1 && by >= 8) {
        Bph = B2h; Bpl = B2l; bp = bias2; bnr = (by - 8) * NT2; is_disp = true;
    } else {
        Bph = Bh;  Bpl = Bl;  bp = bias;  bnr = by * NT2;
    }

    float acc[4][8][4];
#pragma unroll
    for (int mi = 0; mi < 4; mi++)
#pragma unroll
        for (int ni = 0; ni < 8; ni++)
#pragma unroll
            for (int q = 0; q < 4; q++) acc[mi][ni][q] = 0.f;

    const uint32_t sbase = smem_u32(smem);
    const int a_row_in = (lane & 15);
    const int a_col8 = (lane >> 4) * 8;
    const int b_row_in = ((lane >> 4) << 3) + (lane & 7);
    const int b_col8 = ((lane >> 3) & 1) * 8;

    const int l_row = tid >> 2;            // 0..31
    const int l_q = tid & 3;               // 16B quarter

    const int nch = K / KB;

    auto load_stage = [&](int stage, int k0) {
        uint32_t sb = sbase + stage * STAGE_ELEMS * 2;
#pragma unroll
        for (int t = 0; t < 4; t++) {
            int row = l_row + t * 32;      // 0..127
            int so = (row * RS + l_q * 8) * 2;
            size_t go = (size_t)(bm + row) * K + k0 + l_q * 8;
            cp16(sb + so, Ah + go);
            cp16(sb + (128 * RS) * 2 + so, Al + go);
        }
#pragma unroll
        for (int t = 0; t < 4; t++) {
            int row = l_row + t * 32;
            int so = (row * RS + l_q * 8) * 2;
            size_t go = (size_t)(bnr + row) * K + k0 + l_q * 8;
            cp16(sb + (2 * 128 * RS) * 2 + so, Bph + go);
            cp16(sb + (3 * 128 * RS) * 2 + so, Bpl + go);
        }
    };

    load_stage(0, 0);
    CP_COMMIT();

    for (int ch = 0; ch < nch; ch++) {
        const int cur = ch & 1;
        if (ch + 1 < nch) {
            load_stage(cur ^ 1, (ch + 1) * KB);
            CP_COMMIT();
            CP_WAIT(1);
        } else {
            CP_WAIT(0);
        }
        __syncthreads();

        const uint32_t sb = sbase + cur * STAGE_ELEMS * 2;
        const uint32_t aAh = sb;
        const uint32_t aAl = sb + (128 * RS) * 2;
        const uint32_t aBh = sb + (2 * 128 * RS) * 2;
        const uint32_t aBl = sb + (3 * 128 * RS) * 2;

#pragma unroll
        for (int kst = 0; kst < 2; kst++) {
            const int kc = kst * 16;
            uint32_t ah[4][4], al[4][4];
#pragma unroll
            for (int mi = 0; mi < 4; mi++) {
                int off = ((wm * 64 + mi * 16 + a_row_in) * RS + kc + a_col8) * 2;
                ldsm_x4(ah[mi][0], ah[mi][1], ah[mi][2], ah[mi][3], aAh + off);
                ldsm_x4(al[mi][0], al[mi][1], al[mi][2], al[mi][3], aAl + off);
            }
#pragma unroll
            for (int ng = 0; ng < 4; ng++) {
                int off = ((wn * 64 + ng * 16 + b_row_in) * RS + kc + b_col8) * 2;
                uint32_t h0, h1, h2, h3, lo0, lo1, lo2, lo3;
                ldsm_x4(h0, h1, h2, h3, aBh + off);
                ldsm_x4(lo0, lo1, lo2, lo3, aBl + off);
#pragma unroll
                for (int mi = 0; mi < 4; mi++) {
                    mma_bf16(acc[mi][ng * 2 + 0], ah[mi], h0, h1);
                    mma_bf16(acc[mi][ng * 2 + 0], ah[mi], lo0, lo1);
                    mma_bf16(acc[mi][ng * 2 + 0], al[mi], h0, h1);
                    mma_bf16(acc[mi][ng * 2 + 1], ah[mi], h2, h3);
                    mma_bf16(acc[mi][ng * 2 + 1], ah[mi], lo2, lo3);
                    mma_bf16(acc[mi][ng * 2 + 1], al[mi], h2, h3);
                }
            }
        }
        __syncthreads();
    }

    // ---- epilogue ----
    const int gr = lane >> 2;
    const int gc = (lane & 3) * 2;
#pragma unroll
    for (int mi = 0; mi < 4; mi++) {
#pragma unroll
        for (int ni = 0; ni < 8; ni++) {
            int n = bnr + wn * 64 + ni * 8 + gc;     // global n within chosen weight
            float bx = bp[n], by_ = bp[n + 1];
#pragma unroll
            for (int half = 0; half < 2; half++) {
                int m = bm + wm * 64 + mi * 16 + gr + half * 8;
                float vx = acc[mi][ni][half * 2 + 0] + bx;
                float vy = acc[mi][ni][half * 2 + 1] + by_;
                float2 o; o.x = vx; o.y = vy;
                if (MODE == 1) {
                    int b = m >> 10, t = m & (Tt - 1);
                    if (is_disp) {
                        int h = n >> 4, d = n & (BD - 1);
                        *(float2*)(g_disp + ((size_t)((b * NH + h) * Tt + t)) * BD + d) = o;
                    } else {
                        int h = n >> 6, e = n & (HS - 1);
                        *(float2*)(g_val + ((size_t)((b * NH + h) * Tt + t)) * HS + e) = o;
                    }
                } else {
                    *(float2*)(Cout + (size_t)m * N + n) = o;
                }
            }
        }
    }
}

// ---------------------------------------------------------------------------
// pos_feat[j,k] = sum_e rel[j,e] * W_pos[k,e]   (64x16)
// ---------------------------------------------------------------------------
__global__ void posfeat_kernel(const float* __restrict__ rel,
                               const float* __restrict__ Wpos)
{
    int i = threadIdx.x;
    int j = i >> 4, k = i & 15;
    float s = 0.f;
#pragma unroll
    for (int e = 0; e < BD; e++) s += rel[j * BD + e] * Wpos[k * BD + e];
    g_pos[j * BD + k] = s;
}

// ---------------------------------------------------------------------------
// qproj: g_Q[token][o] = sum_d W_fused[o][d] * g_disp[token][d]
// 2 threads per token (each 16 outputs).
// ---------------------------------------------------------------------------
__global__ __launch_bounds__(256) void qproj_kernel(const float* __restrict__ Wf)
{
    __shared__ float Wfs[32 * BD];
    int tid = threadIdx.x;
    for (int i = tid; i < 32 * BD; i += 256) Wfs[i] = Wf[i];
    __syncthreads();

    int gidx = blockIdx.x * 256 + tid;
    size_t token = gidx >> 1;
    int half = gidx & 1;
    float d[BD];
    const float4* dp = (const float4*)(g_disp + token * BD);
#pragma unroll
    for (int q = 0; q < 4; q++) {
        float4 v = dp[q];
        d[q * 4 + 0] = v.x; d[q * 4 + 1] = v.y;
        d[q * 4 + 2] = v.z; d[q * 4 + 3] = v.w;
    }
    float* qout = g_Q + token * 32 + half * 16;
    const float* wbase = Wfs + half * 16 * BD;
#pragma unroll
    for (int o4 = 0; o4 < 4; o4++) {
        float4 r;
        float s0 = 0.f, s1 = 0.f, s2 = 0.f, s3 = 0.f;
#pragma unroll
        for (int dd = 0; dd < BD; dd++) {
            s0 += wbase[(o4 * 4 + 0) * BD + dd] * d[dd];
            s1 += wbase[(o4 * 4 + 1) * BD + dd] * d[dd];
            s2 += wbase[(o4 * 4 + 2) * BD + dd] * d[dd];
            s3 += wbase[(o4 * 4 + 3) * BD + dd] * d[dd];
        }
        r.x = s0; r.y = s1; r.z = s2; r.w = s3;
        *(float4*)(qout + o4 * 4) = r;
    }
}

// ---------------------------------------------------------------------------
// Attention: one block (256 threads) per (b,h, 64-wide t-tile).
// Epilogue writes split-bf16 yh/yl directly.
// ---------------------------------------------------------------------------
struct AttnSmem {
    float QsT[32][132];
    float posB[16][64];
    float Wbs[16];
    float Wds[16];
    float Vs[127][64];
    float Wt[64][68];
};

__global__ __launch_bounds__(256) void attn_kernel(
    const float* __restrict__ b_fused,
    const float* __restrict__ W_bond, const float* __restrict__ b_bond,
    const float* __restrict__ W_dmg,  const float* __restrict__ b_dmg)
{
    extern __shared__ char smraw[];
    AttnSmem& sm = *reinterpret_cast<AttnSmem*>(smraw);

    const int bid = blockIdx.x;
    const int tile = bid & 15;
    const int bh = bid >> 4;
    const int t0 = tile * 64;
    const int tid = threadIdx.x;

    const float* __restrict__ Qbase = g_Q + (size_t)bh * Tt * 32;
    const float* __restrict__ Vbase = g_val + (size_t)bh * Tt * HS;

    for (int i = tid; i < 127 * 8; i += 256) {
        int r = i >> 3, kq = (i & 7) << 2;
        int tp = t0 - 63 + r;
        float4 v = make_float4(0.f, 0.f, 0.f, 0.f);
        if (tp >= 0) v = *(const float4*)(Qbase + (size_t)tp * 32 + kq);
        sm.QsT[kq + 0][r] = v.x; sm.QsT[kq + 1][r] = v.y;
        sm.QsT[kq + 2][r] = v.z; sm.QsT[kq + 3][r] = v.w;
    }
    for (int i = tid; i < 16 * 64; i += 256) {
        int k = i >> 6, j = i & 63;
        sm.posB[k][j] = g_pos[j * BD + k] + b_fused[k];
    }
    if (tid < 16) { sm.Wbs[tid] = W_bond[tid]; sm.Wds[tid] = W_dmg[tid]; }
    for (int i = tid; i < 127 * 16; i += 256) {
        int r = i >> 4, eq = (i & 15) << 2;
        int tp = t0 - 63 + r;
        float4 v = make_float4(0.f, 0.f, 0.f, 0.f);
        if (tp >= 0) v = *(const float4*)(Vbase + (size_t)tp * HS + eq);
        *(float4*)&sm.Vs[r][eq] = v;
    }
    __syncthreads();

    const int tq = tid & 63;
    const int jc = tid >> 6;
    const int c = tq + 63;

    float bond[16], dmg[16];
#pragma unroll
    for (int jj = 0; jj < 16; jj++) { bond[jj] = 0.f; dmg[jj] = 0.f; }

#pragma unroll
    for (int k = 0; k < 16; k++) {
        float qbc = sm.QsT[k][c];
        float qdc = sm.QsT[16 + k][c] - b_fused[16 + k];
        float wb = sm.Wbs[k];
        float wd = sm.Wds[k];
#pragma unroll
        for (int jj = 0; jj < 16; jj++) {
            int j = jc * 16 + jj;
            int r = tq + j;
            float db = sm.QsT[k][r] - qbc + sm.posB[k][j];
            float dd = sm.QsT[16 + k][r] - qdc;
            float argb = db * (0.7978845608f + 0.0356774081f * db * db);
            float argd = dd * (0.7978845608f + 0.0356774081f * dd * dd);
            float thb, thd;
            asm("tanh.approx.f32 %0, %1;" : "=f"(thb) : "f"(argb));
            asm("tanh.approx.f32 %0, %1;" : "=f"(thd) : "f"(argd));
            bond[jj] += 0.5f * db * (1.f + thb) * wb;
            dmg[jj]  += 0.5f * dd * (1.f + thd) * wd;
        }
    }
    {
        float bb = b_bond[0];
        float bdm = b_dmg[0];
#pragma unroll
        for (int jj = 0; jj < 16; jj++) {
            int j = jc * 16 + jj;
            float sig = 1.f / (1.f + __expf(-(dmg[jj] + bdm)));
            float logit = bond[jj] + bb - 10.f * sig;
            if (t0 + tq - 63 + j < 0) logit = -CUDART_INF_F;
            sm.Wt[tq][j] = logit;
        }
    }
    __syncthreads();

    if (tid < 64) {
        float mx = -CUDART_INF_F;
#pragma unroll
        for (int j = 0; j < 64; j++) mx = fmaxf(mx, sm.Wt[tid][j]);
        float s = 0.f;
#pragma unroll
        for (int j = 0; j < 64; j++) {
            float e = __expf(sm.Wt[tid][j] - mx);
            sm.Wt[tid][j] = e;
            s += e;
        }
        float inv = 1.f / s;
#pragma unroll
        for (int j = 0; j < 64; j++) sm.Wt[tid][j] *= inv;
    }
    __syncthreads();

    const int wrp = tid >> 5;
    const int l = tid & 31;
    const int b = bh >> 4;
    const int h = bh & (NH - 1);

    for (int q = 0; q < 8; q++) {
        int t = wrp * 8 + q;
        unsigned long long acc = 0ULL;
#pragma unroll
        for (int j = 0; j < 64; j += 4) {
            float4 wv = *(const float4*)&sm.Wt[t][j];
            fma2(acc, pack2(wv.x, wv.x),
                 *(const unsigned long long*)&sm.Vs[t + j + 0][2 * l]);
            fma2(acc, pack2(wv.y, wv.y),
                 *(const unsigned long long*)&sm.Vs[t + j + 1][2 * l]);
            fma2(acc, pack2(wv.z, wv.z),
                 *(const unsigned long long*)&sm.Vs[t + j + 2][2 * l]);
            fma2(acc, pack2(wv.w, wv.w),
                 *(const unsigned long long*)&sm.Vs[t + j + 3][2 * l]);
        }
        float ox, oy;
        unpack2(acc, ox, oy);
        __nv_bfloat16 h0 = __float2bfloat16(ox);
        __nv_bfloat16 h1 = __float2bfloat16(oy);
        __nv_bfloat16 l0 = __float2bfloat16(ox - __bfloat162float(h0));
        __nv_bfloat16 l1 = __float2bfloat16(oy - __bfloat162float(h1));
        size_t idx = ((size_t)(b * Tt + t0 + t)) * Cc + h * HS + 2 * l;
        __nv_bfloat162 hv; hv.x = h0; hv.y = h1;
        __nv_bfloat162 lv; lv.x = l0; lv.y = l1;
        *(__nv_bfloat162*)(g_yh + idx) = hv;
        *(__nv_bfloat162*)(g_yl + idx) = lv;
    }
}

// ---------------------------------------------------------------------------
// Launch
// ---------------------------------------------------------------------------
extern "C" void kernel_launch(void* const* d_in, const int* in_sizes, int n_in,
                              void* d_out, int out_size)
{
    const float* x       = (const float*)d_in[0];
    const float* W_disp  = (const float*)d_in[1];
    const float* b_disp  = (const float*)d_in[2];
    const float* W_val   = (const float*)d_in[3];
    const float* b_val   = (const float*)d_in[4];
    const float* rel     = (const float*)d_in[5];
    const float* W_fused = (const float*)d_in[6];
    const float* b_fused = (const float*)d_in[7];
    const float* W_pos   = (const float*)d_in[8];
    const float* W_bond  = (const float*)d_in[9];
    const float* b_bond  = (const float*)d_in[10];
    const float* W_dmg   = (const float*)d_in[11];
    const float* b_dmg   = (const float*)d_in[12];
    const float* W_cproj = (const float*)d_in[13];
    const float* b_cproj = (const float*)d_in[14];
    float* out = (float*)d_out;

    const int M = Bb * Tt;   // 2048
    const int K = Cc;        // 1024

    __nv_bfloat16 *xh, *xl, *wdh, *wdl, *wvh, *wvl, *wch, *wcl, *yh, *yl;
    void* p;
    cudaGetSymbolAddress(&p, g_xh);  xh  = (__nv_bfloat16*)p;
    cudaGetSymbolAddress(&p, g_xl);  xl  = (__nv_bfloat16*)p;
    cudaGetSymbolAddress(&p, g_wdh); wdh = (__nv_bfloat16*)p;
    cudaGetSymbolAddress(&p, g_wdl); wdl = (__nv_bfloat16*)p;
    cudaGetSymbolAddress(&p, g_wvh); wvh = (__nv_bfloat16*)p;
    cudaGetSymbolAddress(&p, g_wvl); wvl = (__nv_bfloat16*)p;
    cudaGetSymbolAddress(&p, g_wch); wch = (__nv_bfloat16*)p;
    cudaGetSymbolAddress(&p, g_wcl); wcl = (__nv_bfloat16*)p;
    cudaGetSymbolAddress(&p, g_yh);  yh  = (__nv_bfloat16*)p;
    cudaGetSymbolAddress(&p, g_yl);  yl  = (__nv_bfloat16*)p;

    // 0: fused splits (x, W_val, W_cproj, W_disp) — one launch
    split_fused<<<4352, 256>>>(x, W_val, W_cproj, W_disp);

    const int SMEM_BIG = STAGE_ELEMS * 2 * 2;   // 81920 bytes
    cudaFuncSetAttribute(mma_gemm_big<1>, cudaFuncAttributeMaxDynamicSharedMemorySize, SMEM_BIG);
    cudaFuncSetAttribute(mma_gemm_big<2>, cudaFuncAttributeMaxDynamicSharedMemorySize, SMEM_BIG);

    // 1: fused val + disp GEMM (grid.y: 0-7 val, 8-9 disp)
    dim3 gvd(M / MT, 10);
    mma_gemm_big<1><<<gvd, 128, SMEM_BIG>>>(xh, xl, wvh, wvl, wdh, wdl,
                                            b_val, b_disp, nullptr, M, Cc, K);

    // 2, 3: tiny precomputes
    posfeat_kernel<<<1, DELTA * BD>>>(rel, W_pos);
    qproj_kernel<<<(2 * Bb * NH * Tt) / 256, 256>>>(W_fused);

    // 4: attention (writes split-bf16 y directly)
    cudaFuncSetAttribute(attn_kernel, cudaFuncAttributeMaxDynamicSharedMemorySize,
                         (int)sizeof(AttnSmem));
    attn_kernel<<<Bb * NH * (Tt / DELTA), 256, sizeof(AttnSmem)>>>(
        b_fused, W_bond, b_bond, W_dmg, b_dmg);

    // 5: cproj GEMM -> out   (lands on ncu -s 5 -c 1 for visibility)
    dim3 gc(M / MT, 8);
    mma_gemm_big<2><<<gc, 128, SMEM_BIG>>>(yh, yl, wch, wcl, nullptr, nullptr,
                                           b_cproj, nullptr, out, M, Cc, K);
}